// round 3
// baseline (speedup 1.0000x reference)
#include <cuda_runtime.h>

#define N_NODES 50000
#define N_EDGES 800000
#define N_RELS  8
// feature dims: 64 -> 64 -> 32, K per segment is always 64

// Scratch (device globals; no allocation allowed in kernel_launch)
__device__ float g_acc[(size_t)N_RELS * N_NODES * 64];  // 102.4 MB accumulator
__device__ float g_h[(size_t)N_NODES * 64];             // layer-1 output (post-ReLU)
__device__ int   g_cnt[N_NODES * N_RELS];
__device__ float g_inv[N_NODES * N_RELS];

// ---------------------------------------------------------------------------
__global__ void zero_cnt_k() {
    int i = blockIdx.x * blockDim.x + threadIdx.x;
    if (i < N_NODES * N_RELS) g_cnt[i] = 0;
}

__global__ void count_k(const int* __restrict__ ei,
                        const int* __restrict__ et) {
    int e = blockIdx.x * blockDim.x + threadIdx.x;
    if (e < N_EDGES) {
        int dst = ei[N_EDGES + e];
        int r   = et[e];
        atomicAdd(&g_cnt[dst * N_RELS + r], 1);
    }
}

__global__ void inv_k() {
    int i = blockIdx.x * blockDim.x + threadIdx.x;
    if (i < N_NODES * N_RELS) {
        int c = g_cnt[i];
        g_inv[i] = 1.0f / (float)(c > 1 ? c : 1);
    }
}

// 25,600,000 floats = 6,400,000 float4 = 25000 blocks x 256 threads exactly
__global__ void zero_acc_k() {
    int i = blockIdx.x * blockDim.x + threadIdx.x;
    ((float4*)g_acc)[i] = make_float4(0.f, 0.f, 0.f, 0.f);
}

// ---------------------------------------------------------------------------
// Scatter: acc[et][dst][:] += X[src][:] * inv_cnt(dst,et)
// 4 threads per edge, each handles 16 floats via scalar atomicAdd (REDG.32)
__global__ void scatter_k(const float* __restrict__ X,
                          const int* __restrict__ ei,
                          const int* __restrict__ et) {
    int gid = blockIdx.x * blockDim.x + threadIdx.x;
    int e = gid >> 2;
    int q = gid & 3;
    if (e >= N_EDGES) return;
    int src = ei[e];
    int dst = ei[N_EDGES + e];
    int r   = et[e];
    float w = g_inv[dst * N_RELS + r];

    const float4* x4 = (const float4*)(X + (size_t)src * 64) + q * 4;
    float* outp = g_acc + ((size_t)r * N_NODES + (size_t)dst) * 64 + q * 16;

    #pragma unroll
    for (int i = 0; i < 4; i++) {
        float4 v = x4[i];
        atomicAdd(outp + i * 4 + 0, v.x * w);
        atomicAdd(outp + i * 4 + 1, v.y * w);
        atomicAdd(outp + i * 4 + 2, v.z * w);
        atomicAdd(outp + i * 4 + 3, v.w * w);
    }
}

// ---------------------------------------------------------------------------
// Fused GEMM over 9 segments: out = X@root + sum_r acc[r]@W[r] + bias (opt relu)
// Block: 256 threads (16x16), tile = 64 rows x FOUT cols, K=64 per segment.
template<int FOUT, bool RELU>
__global__ __launch_bounds__(256)
void gemm_k(const float* __restrict__ X,      // [N,64]
            const float* __restrict__ root,   // [64,FOUT]
            const float* __restrict__ Wr,     // [R,64,FOUT]
            const float* __restrict__ bias,   // [FOUT]
            float* __restrict__ out)          // [N,FOUT]
{
    __shared__ float As[64 * 64];
    __shared__ float Ws[64 * FOUT];

    const int tid = threadIdx.x;
    const int tx = tid & 15;
    const int ty = tid >> 4;
    const int row0 = blockIdx.x * 64;
    constexpr int CJ = FOUT / 16;

    float acc[4][CJ];
    #pragma unroll
    for (int i = 0; i < 4; i++)
        #pragma unroll
        for (int j = 0; j < CJ; j++) acc[i][j] = 0.f;

    for (int seg = 0; seg < 9; seg++) {
        const float* A = (seg == 0) ? X : (g_acc + (size_t)(seg - 1) * N_NODES * 64);
        const float* W = (seg == 0) ? root : (Wr + (size_t)(seg - 1) * 64 * FOUT);

        // Load A tile: 64x64 floats = 1024 float4, 4 per thread (coalesced rows)
        #pragma unroll
        for (int i = 0; i < 4; i++) {
            int lin = tid + i * 256;     // float4 index in tile
            int r = lin >> 4, c4 = lin & 15;
            int grow = row0 + r;
            float4 v = make_float4(0.f, 0.f, 0.f, 0.f);
            if (grow < N_NODES) v = ((const float4*)(A + (size_t)grow * 64))[c4];
            ((float4*)As)[lin] = v;
        }
        // Load W tile: 64*FOUT floats, linear copy
        constexpr int WF4 = 64 * FOUT / 4;
        #pragma unroll
        for (int i = 0; i < WF4 / 256; i++) {
            int lin = tid + i * 256;
            ((float4*)Ws)[lin] = ((const float4*)W)[lin];
        }
        __syncthreads();

        #pragma unroll
        for (int k = 0; k < 64; k++) {
            float wv[CJ];
            #pragma unroll
            for (int j = 0; j < CJ; j++) wv[j] = Ws[k * FOUT + tx + 16 * j];
            #pragma unroll
            for (int i = 0; i < 4; i++) {
                float a = As[(ty + 16 * i) * 64 + k];
                #pragma unroll
                for (int j = 0; j < CJ; j++)
                    acc[i][j] = fmaf(a, wv[j], acc[i][j]);
            }
        }
        __syncthreads();
    }

    #pragma unroll
    for (int i = 0; i < 4; i++) {
        int grow = row0 + ty + 16 * i;
        if (grow < N_NODES) {
            #pragma unroll
            for (int j = 0; j < CJ; j++) {
                int c = tx + 16 * j;
                float v = acc[i][j] + bias[c];
                if (RELU) v = fmaxf(v, 0.f);
                out[(size_t)grow * FOUT + c] = v;
            }
        }
    }
}

// ---------------------------------------------------------------------------
extern "C" void kernel_launch(void* const* d_in, const int* in_sizes, int n_in,
                              void* d_out, int out_size) {
    const float* x     = (const float*)d_in[0];
    const int*   ei    = (const int*)d_in[1];   // int32 on device (JAX x64 off)
    const int*   et    = (const int*)d_in[2];   // int32 on device
    const float* W1    = (const float*)d_in[3];
    const float* root1 = (const float*)d_in[4];
    const float* b1    = (const float*)d_in[5];
    const float* W2    = (const float*)d_in[6];
    const float* root2 = (const float*)d_in[7];
    const float* b2    = (const float*)d_in[8];
    float* out = (float*)d_out;

    float* h_ptr = nullptr;
    cudaGetSymbolAddress((void**)&h_ptr, g_h);

    const int segBlocks  = (N_NODES * N_RELS + 255) / 256;
    const int edgeBlocks = (N_EDGES + 255) / 256;
    const int scatBlocks = (N_EDGES * 4 + 255) / 256;
    const int gemmBlocks = (N_NODES + 63) / 64;

    // Edge normalization (shared by both layers)
    zero_cnt_k<<<segBlocks, 256>>>();
    count_k<<<edgeBlocks, 256>>>(ei, et);
    inv_k<<<segBlocks, 256>>>();

    // Layer 1
    zero_acc_k<<<25000, 256>>>();
    scatter_k<<<scatBlocks, 256>>>(x, ei, et);
    gemm_k<64, true><<<gemmBlocks, 256>>>(x, root1, W1, b1, h_ptr);

    // Layer 2
    zero_acc_k<<<25000, 256>>>();
    scatter_k<<<scatBlocks, 256>>>(h_ptr, ei, et);
    gemm_k<32, false><<<gemmBlocks, 256>>>(h_ptr, root2, W2, b2, out);
}

// round 4
// speedup vs baseline: 1.9185x; 1.9185x over previous
#include <cuda_runtime.h>

#define N_NODES 50000
#define N_EDGES 800000
#define N_RELS  8
// feature dims: 64 -> 64 -> 32, K per segment is always 64

// Scratch (device globals; no allocation allowed in kernel_launch)
__device__ float g_acc[(size_t)N_RELS * N_NODES * 64];  // 102.4 MB accumulator
__device__ float g_h[(size_t)N_NODES * 64];             // layer-1 output (post-ReLU)
__device__ int   g_cnt[N_NODES * N_RELS];
__device__ float g_inv[N_NODES * N_RELS];

// ---------------------------------------------------------------------------
__global__ void zero_cnt_k() {
    int i = blockIdx.x * blockDim.x + threadIdx.x;
    if (i < N_NODES * N_RELS) g_cnt[i] = 0;
}

__global__ void count_k(const int* __restrict__ ei,
                        const int* __restrict__ et) {
    int e = blockIdx.x * blockDim.x + threadIdx.x;
    if (e < N_EDGES) {
        int dst = ei[N_EDGES + e];
        int r   = et[e];
        atomicAdd(&g_cnt[dst * N_RELS + r], 1);
    }
}

__global__ void inv_k() {
    int i = blockIdx.x * blockDim.x + threadIdx.x;
    if (i < N_NODES * N_RELS) {
        int c = g_cnt[i];
        g_inv[i] = 1.0f / (float)(c > 1 ? c : 1);
    }
}

// 25,600,000 floats = 6,400,000 float4 = 25000 blocks x 256 threads exactly
__global__ void zero_acc_k() {
    int i = blockIdx.x * blockDim.x + threadIdx.x;
    ((float4*)g_acc)[i] = make_float4(0.f, 0.f, 0.f, 0.f);
}

// ---------------------------------------------------------------------------
// Scatter: acc[et][dst][:] += X[src][:] * inv_cnt(dst,et)
// 4 threads per edge, each handles 16 floats via 4x red.global.add.v4.f32
__global__ void scatter_k(const float* __restrict__ X,
                          const int* __restrict__ ei,
                          const int* __restrict__ et) {
    int gid = blockIdx.x * blockDim.x + threadIdx.x;
    int e = gid >> 2;
    int q = gid & 3;
    if (e >= N_EDGES) return;
    int src = ei[e];
    int dst = ei[N_EDGES + e];
    int r   = et[e];
    float w = g_inv[dst * N_RELS + r];

    const float4* x4 = (const float4*)(X + (size_t)src * 64) + q * 4;
    float* outp = g_acc + ((size_t)r * N_NODES + (size_t)dst) * 64 + q * 16;

    #pragma unroll
    for (int i = 0; i < 4; i++) {
        float4 v = x4[i];
        v.x *= w; v.y *= w; v.z *= w; v.w *= w;
        asm volatile(
            "red.global.add.v4.f32 [%0], {%1, %2, %3, %4};"
            :: "l"(outp + i * 4), "f"(v.x), "f"(v.y), "f"(v.z), "f"(v.w)
            : "memory");
    }
}

// ---------------------------------------------------------------------------
// Fused GEMM over 9 segments: out = X@root + sum_r acc[r]@W[r] + bias (opt relu)
// Block: 256 threads (16x16), tile = 64 rows x FOUT cols, K=64 per segment.
template<int FOUT, bool RELU>
__global__ __launch_bounds__(256)
void gemm_k(const float* __restrict__ X,      // [N,64]
            const float* __restrict__ root,   // [64,FOUT]
            const float* __restrict__ Wr,     // [R,64,FOUT]
            const float* __restrict__ bias,   // [FOUT]
            float* __restrict__ out)          // [N,FOUT]
{
    __shared__ float As[64 * 64];
    __shared__ float Ws[64 * FOUT];

    const int tid = threadIdx.x;
    const int tx = tid & 15;
    const int ty = tid >> 4;
    const int row0 = blockIdx.x * 64;
    constexpr int CJ = FOUT / 16;

    float acc[4][CJ];
    #pragma unroll
    for (int i = 0; i < 4; i++)
        #pragma unroll
        for (int j = 0; j < CJ; j++) acc[i][j] = 0.f;

    for (int seg = 0; seg < 9; seg++) {
        const float* A = (seg == 0) ? X : (g_acc + (size_t)(seg - 1) * N_NODES * 64);
        const float* W = (seg == 0) ? root : (Wr + (size_t)(seg - 1) * 64 * FOUT);

        // Load A tile: 64x64 floats = 1024 float4, 4 per thread (coalesced rows)
        #pragma unroll
        for (int i = 0; i < 4; i++) {
            int lin = tid + i * 256;     // float4 index in tile
            int r = lin >> 4, c4 = lin & 15;
            int grow = row0 + r;
            float4 v = make_float4(0.f, 0.f, 0.f, 0.f);
            if (grow < N_NODES) v = ((const float4*)(A + (size_t)grow * 64))[c4];
            ((float4*)As)[lin] = v;
        }
        // Load W tile: 64*FOUT floats, linear copy
        constexpr int WF4 = 64 * FOUT / 4;
        #pragma unroll
        for (int i = 0; i < WF4 / 256; i++) {
            int lin = tid + i * 256;
            ((float4*)Ws)[lin] = ((const float4*)W)[lin];
        }
        __syncthreads();

        #pragma unroll
        for (int k = 0; k < 64; k++) {
            float wv[CJ];
            #pragma unroll
            for (int j = 0; j < CJ; j++) wv[j] = Ws[k * FOUT + tx + 16 * j];
            #pragma unroll
            for (int i = 0; i < 4; i++) {
                float a = As[(ty + 16 * i) * 64 + k];
                #pragma unroll
                for (int j = 0; j < CJ; j++)
                    acc[i][j] = fmaf(a, wv[j], acc[i][j]);
            }
        }
        __syncthreads();
    }

    #pragma unroll
    for (int i = 0; i < 4; i++) {
        int grow = row0 + ty + 16 * i;
        if (grow < N_NODES) {
            #pragma unroll
            for (int j = 0; j < CJ; j++) {
                int c = tx + 16 * j;
                float v = acc[i][j] + bias[c];
                if (RELU) v = fmaxf(v, 0.f);
                out[(size_t)grow * FOUT + c] = v;
            }
        }
    }
}

// ---------------------------------------------------------------------------
extern "C" void kernel_launch(void* const* d_in, const int* in_sizes, int n_in,
                              void* d_out, int out_size) {
    const float* x     = (const float*)d_in[0];
    const int*   ei    = (const int*)d_in[1];   // int32 on device (JAX x64 off)
    const int*   et    = (const int*)d_in[2];   // int32 on device
    const float* W1    = (const float*)d_in[3];
    const float* root1 = (const float*)d_in[4];
    const float* b1    = (const float*)d_in[5];
    const float* W2    = (const float*)d_in[6];
    const float* root2 = (const float*)d_in[7];
    const float* b2    = (const float*)d_in[8];
    float* out = (float*)d_out;

    float* h_ptr = nullptr;
    cudaGetSymbolAddress((void**)&h_ptr, g_h);

    const int segBlocks  = (N_NODES * N_RELS + 255) / 256;
    const int edgeBlocks = (N_EDGES + 255) / 256;
    const int scatBlocks = (N_EDGES * 4 + 255) / 256;
    const int gemmBlocks = (N_NODES + 63) / 64;

    // Edge normalization (shared by both layers)
    zero_cnt_k<<<segBlocks, 256>>>();
    count_k<<<edgeBlocks, 256>>>(ei, et);
    inv_k<<<segBlocks, 256>>>();

    // Layer 1
    zero_acc_k<<<25000, 256>>>();
    scatter_k<<<scatBlocks, 256>>>(x, ei, et);
    gemm_k<64, true><<<gemmBlocks, 256>>>(x, root1, W1, b1, h_ptr);

    // Layer 2
    zero_acc_k<<<25000, 256>>>();
    scatter_k<<<scatBlocks, 256>>>(h_ptr, ei, et);
    gemm_k<32, false><<<gemmBlocks, 256>>>(h_ptr, root2, W2, b2, out);
}

// round 5
// speedup vs baseline: 2.1732x; 1.1327x over previous
#include <cuda_runtime.h>

#define N_NODES 50000
#define N_EDGES 800000
#define N_RELS  8
#define NSEG    (N_NODES * N_RELS)       // 400000 segments, key = dst*8 + rel
#define SCAN_CHUNK 2048
#define NCHUNK  ((NSEG + SCAN_CHUNK - 1) / SCAN_CHUNK)   // 196

// Scratch (device globals; no allocation allowed anywhere)
__device__ float g_acc[(size_t)NSEG * 64];   // [dst][rel][64] = 102.4 MB
__device__ float g_h[(size_t)N_NODES * 64];  // layer-1 output (post-ReLU)
__device__ int   g_cnt[NSEG];
__device__ float g_inv[NSEG];
__device__ int   g_off[NSEG];                // CSR segment start
__device__ int   g_cur[NSEG];                // fill cursors
__device__ int   g_bsum[NCHUNK];
__device__ int   g_srcs[N_EDGES];            // src ids sorted by segment

// ---------------------------------------------------------------------------
__global__ void zero_cnt_k() {
    int i = blockIdx.x * blockDim.x + threadIdx.x;
    if (i < NSEG) g_cnt[i] = 0;
}

__global__ void count_k(const int* __restrict__ ei,
                        const int* __restrict__ et) {
    int e = blockIdx.x * blockDim.x + threadIdx.x;
    if (e < N_EDGES) {
        int dst = ei[N_EDGES + e];
        int r   = et[e];
        atomicAdd(&g_cnt[dst * N_RELS + r], 1);
    }
}

__global__ void inv_k() {
    int i = blockIdx.x * blockDim.x + threadIdx.x;
    if (i < NSEG) {
        int c = g_cnt[i];
        g_inv[i] = 1.0f / (float)(c > 1 ? c : 1);
    }
}

// --- 3-phase exclusive scan of g_cnt -> g_off ------------------------------
__global__ void scan1_k() {  // grid NCHUNK, block 256; each thread 8 elems
    __shared__ int sh[256];
    int t = threadIdx.x;
    int base = blockIdx.x * SCAN_CHUNK + t * 8;
    int v[8]; int s = 0;
    #pragma unroll
    for (int i = 0; i < 8; i++) {
        int idx = base + i;
        v[i] = (idx < NSEG) ? g_cnt[idx] : 0;
        s += v[i];
    }
    sh[t] = s;
    __syncthreads();
    for (int off = 1; off < 256; off <<= 1) {
        int u = (t >= off) ? sh[t - off] : 0;
        __syncthreads();
        sh[t] += u;
        __syncthreads();
    }
    if (t == 255) g_bsum[blockIdx.x] = sh[255];
    int run = sh[t] - s;   // exclusive prefix of this thread's chunk
    #pragma unroll
    for (int i = 0; i < 8; i++) {
        if (base + i < NSEG) g_off[base + i] = run;
        run += v[i];
    }
}

__global__ void scan2_k() {  // 1 block, 256 threads; scans NCHUNK totals
    __shared__ int sh[256];
    int t = threadIdx.x;
    int s = (t < NCHUNK) ? g_bsum[t] : 0;
    sh[t] = s;
    __syncthreads();
    for (int off = 1; off < 256; off <<= 1) {
        int u = (t >= off) ? sh[t - off] : 0;
        __syncthreads();
        sh[t] += u;
        __syncthreads();
    }
    if (t < NCHUNK) g_bsum[t] = sh[t] - s;  // exclusive
}

__global__ void scan3_k() {  // finalize offsets + init cursors
    int i = blockIdx.x * blockDim.x + threadIdx.x;
    if (i < NSEG) {
        int o = g_off[i] + g_bsum[i >> 11];   // 2048 = 1<<11
        g_off[i] = o;
        g_cur[i] = o;
    }
}

__global__ void fill_k(const int* __restrict__ ei,
                       const int* __restrict__ et) {
    int e = blockIdx.x * blockDim.x + threadIdx.x;
    if (e < N_EDGES) {
        int src = ei[e];
        int dst = ei[N_EDGES + e];
        int r   = et[e];
        int p = atomicAdd(&g_cur[dst * N_RELS + r], 1);
        g_srcs[p] = src;
    }
}

// ---------------------------------------------------------------------------
// Gather-aggregate: acc[seg][:] = inv[seg] * sum_{e in seg} X[src(e)][:]
// 4 threads per segment, each handles 16 floats. Plain stores, no atomics.
__global__ void agg_k(const float* __restrict__ X) {
    int gid = blockIdx.x * blockDim.x + threadIdx.x;
    int seg = gid >> 2;
    int q = gid & 3;
    if (seg >= NSEG) return;
    int start = g_off[seg];
    int cnt = g_cnt[seg];

    float4 s0 = make_float4(0.f, 0.f, 0.f, 0.f);
    float4 s1 = s0, s2 = s0, s3 = s0;
    for (int i = 0; i < cnt; i++) {
        int src = g_srcs[start + i];
        const float4* xp = (const float4*)(X + (size_t)src * 64) + q * 4;
        float4 a = xp[0], b = xp[1], c = xp[2], d = xp[3];
        s0.x += a.x; s0.y += a.y; s0.z += a.z; s0.w += a.w;
        s1.x += b.x; s1.y += b.y; s1.z += b.z; s1.w += b.w;
        s2.x += c.x; s2.y += c.y; s2.z += c.z; s2.w += c.w;
        s3.x += d.x; s3.y += d.y; s3.z += d.z; s3.w += d.w;
    }
    float w = g_inv[seg];
    s0.x *= w; s0.y *= w; s0.z *= w; s0.w *= w;
    s1.x *= w; s1.y *= w; s1.z *= w; s1.w *= w;
    s2.x *= w; s2.y *= w; s2.z *= w; s2.w *= w;
    s3.x *= w; s3.y *= w; s3.z *= w; s3.w *= w;

    float4* op = (float4*)(g_acc + (size_t)seg * 64) + q * 4;
    op[0] = s0; op[1] = s1; op[2] = s2; op[3] = s3;
}

// ---------------------------------------------------------------------------
// Fused GEMM over 9 segments: out = X@root + sum_r acc_r@W[r] + bias (opt relu)
// acc layout is [dst][rel][64] -> relation-r rows have stride 512 floats.
template<int FOUT, bool RELU>
__global__ __launch_bounds__(256)
void gemm_k(const float* __restrict__ X,      // [N,64] stride 64
            const float* __restrict__ root,   // [64,FOUT]
            const float* __restrict__ Wr,     // [R,64,FOUT]
            const float* __restrict__ bias,   // [FOUT]
            float* __restrict__ out)          // [N,FOUT]
{
    __shared__ float As[64 * 64];
    __shared__ float Ws[64 * FOUT];

    const int tid = threadIdx.x;
    const int tx = tid & 15;
    const int ty = tid >> 4;
    const int row0 = blockIdx.x * 64;
    constexpr int CJ = FOUT / 16;

    float acc[4][CJ];
    #pragma unroll
    for (int i = 0; i < 4; i++)
        #pragma unroll
        for (int j = 0; j < CJ; j++) acc[i][j] = 0.f;

    for (int seg = 0; seg < 9; seg++) {
        const float* W = (seg == 0) ? root : (Wr + (size_t)(seg - 1) * 64 * FOUT);

        // Load A tile: 64 rows x 64 cols = 1024 float4, 4 per thread
        #pragma unroll
        for (int i = 0; i < 4; i++) {
            int lin = tid + i * 256;
            int r = lin >> 4, c4 = lin & 15;
            int grow = row0 + r;
            float4 v = make_float4(0.f, 0.f, 0.f, 0.f);
            if (grow < N_NODES) {
                const float4* src4 = (seg == 0)
                    ? (const float4*)(X + (size_t)grow * 64)
                    : (const float4*)(g_acc + (size_t)grow * 512 + (seg - 1) * 64);
                v = src4[c4];
            }
            ((float4*)As)[lin] = v;
        }
        // Load W tile
        constexpr int WF4 = 64 * FOUT / 4;
        #pragma unroll
        for (int i = 0; i < WF4 / 256; i++) {
            int lin = tid + i * 256;
            ((float4*)Ws)[lin] = ((const float4*)W)[lin];
        }
        __syncthreads();

        #pragma unroll
        for (int k = 0; k < 64; k++) {
            float wv[CJ];
            #pragma unroll
            for (int j = 0; j < CJ; j++) wv[j] = Ws[k * FOUT + tx + 16 * j];
            #pragma unroll
            for (int i = 0; i < 4; i++) {
                float a = As[(ty + 16 * i) * 64 + k];
                #pragma unroll
                for (int j = 0; j < CJ; j++)
                    acc[i][j] = fmaf(a, wv[j], acc[i][j]);
            }
        }
        __syncthreads();
    }

    #pragma unroll
    for (int i = 0; i < 4; i++) {
        int grow = row0 + ty + 16 * i;
        if (grow < N_NODES) {
            #pragma unroll
            for (int j = 0; j < CJ; j++) {
                int c = tx + 16 * j;
                float v = acc[i][j] + bias[c];
                if (RELU) v = fmaxf(v, 0.f);
                out[(size_t)grow * FOUT + c] = v;
            }
        }
    }
}

// ---------------------------------------------------------------------------
extern "C" void kernel_launch(void* const* d_in, const int* in_sizes, int n_in,
                              void* d_out, int out_size) {
    const float* x     = (const float*)d_in[0];
    const int*   ei    = (const int*)d_in[1];   // int32 on device (JAX x64 off)
    const int*   et    = (const int*)d_in[2];
    const float* W1    = (const float*)d_in[3];
    const float* root1 = (const float*)d_in[4];
    const float* b1    = (const float*)d_in[5];
    const float* W2    = (const float*)d_in[6];
    const float* root2 = (const float*)d_in[7];
    const float* b2    = (const float*)d_in[8];
    float* out = (float*)d_out;

    float* h_ptr = nullptr;
    cudaGetSymbolAddress((void**)&h_ptr, g_h);

    const int segBlocks  = (NSEG + 255) / 256;
    const int edgeBlocks = (N_EDGES + 255) / 256;
    const int aggBlocks  = (NSEG * 4 + 255) / 256;
    const int gemmBlocks = (N_NODES + 63) / 64;

    // CSR build (shared by both layers)
    zero_cnt_k<<<segBlocks, 256>>>();
    count_k<<<edgeBlocks, 256>>>(ei, et);
    inv_k<<<segBlocks, 256>>>();
    scan1_k<<<NCHUNK, 256>>>();
    scan2_k<<<1, 256>>>();
    scan3_k<<<segBlocks, 256>>>();
    fill_k<<<edgeBlocks, 256>>>(ei, et);

    // Layer 1
    agg_k<<<aggBlocks, 256>>>(x);
    gemm_k<64, true><<<gemmBlocks, 256>>>(x, root1, W1, b1, h_ptr);

    // Layer 2
    agg_k<<<aggBlocks, 256>>>(h_ptr);
    gemm_k<32, false><<<gemmBlocks, 256>>>(h_ptr, root2, W2, b2, out);
}

// round 6
// speedup vs baseline: 2.4173x; 1.1123x over previous
#include <cuda_runtime.h>

#define N_NODES 50000
#define N_EDGES 800000
#define N_RELS  8
#define NSEG    (N_NODES * N_RELS)       // 400000 segments, key = dst*8 + rel
#define SCAN_CHUNK 2048
#define NCHUNK  ((NSEG + SCAN_CHUNK - 1) / SCAN_CHUNK)   // 196

// Scratch (device globals; no allocation allowed anywhere)
__device__ float g_h[(size_t)N_NODES * 64];  // layer-1 output (post-ReLU)
__device__ int   g_cnt[NSEG];
__device__ float g_inv[NSEG];
__device__ int   g_off[NSEG];                // CSR segment start
__device__ int   g_cur[NSEG];                // fill cursors
__device__ int   g_bsum[NCHUNK];
__device__ int   g_srcs[N_EDGES];            // src ids sorted by segment

// ---------------------------------------------------------------------------
__global__ void zero_cnt_k() {
    int i = blockIdx.x * blockDim.x + threadIdx.x;
    if (i < NSEG) g_cnt[i] = 0;
}

__global__ void count_k(const int* __restrict__ ei,
                        const int* __restrict__ et) {
    int e = blockIdx.x * blockDim.x + threadIdx.x;
    if (e < N_EDGES) {
        int dst = ei[N_EDGES + e];
        int r   = et[e];
        atomicAdd(&g_cnt[dst * N_RELS + r], 1);
    }
}

__global__ void inv_k() {
    int i = blockIdx.x * blockDim.x + threadIdx.x;
    if (i < NSEG) {
        int c = g_cnt[i];
        g_inv[i] = 1.0f / (float)(c > 1 ? c : 1);
    }
}

// --- 3-phase exclusive scan of g_cnt -> g_off ------------------------------
__global__ void scan1_k() {  // grid NCHUNK, block 256; each thread 8 elems
    __shared__ int sh[256];
    int t = threadIdx.x;
    int base = blockIdx.x * SCAN_CHUNK + t * 8;
    int v[8]; int s = 0;
    #pragma unroll
    for (int i = 0; i < 8; i++) {
        int idx = base + i;
        v[i] = (idx < NSEG) ? g_cnt[idx] : 0;
        s += v[i];
    }
    sh[t] = s;
    __syncthreads();
    for (int off = 1; off < 256; off <<= 1) {
        int u = (t >= off) ? sh[t - off] : 0;
        __syncthreads();
        sh[t] += u;
        __syncthreads();
    }
    if (t == 255) g_bsum[blockIdx.x] = sh[255];
    int run = sh[t] - s;   // exclusive prefix of this thread's chunk
    #pragma unroll
    for (int i = 0; i < 8; i++) {
        if (base + i < NSEG) g_off[base + i] = run;
        run += v[i];
    }
}

__global__ void scan2_k() {  // 1 block, 256 threads; scans NCHUNK totals
    __shared__ int sh[256];
    int t = threadIdx.x;
    int s = (t < NCHUNK) ? g_bsum[t] : 0;
    sh[t] = s;
    __syncthreads();
    for (int off = 1; off < 256; off <<= 1) {
        int u = (t >= off) ? sh[t - off] : 0;
        __syncthreads();
        sh[t] += u;
        __syncthreads();
    }
    if (t < NCHUNK) g_bsum[t] = sh[t] - s;  // exclusive
}

__global__ void scan3_k() {  // finalize offsets + init cursors
    int i = blockIdx.x * blockDim.x + threadIdx.x;
    if (i < NSEG) {
        int o = g_off[i] + g_bsum[i >> 11];   // 2048 = 1<<11
        g_off[i] = o;
        g_cur[i] = o;
    }
}

__global__ void fill_k(const int* __restrict__ ei,
                       const int* __restrict__ et) {
    int e = blockIdx.x * blockDim.x + threadIdx.x;
    if (e < N_EDGES) {
        int src = ei[e];
        int dst = ei[N_EDGES + e];
        int r   = et[e];
        int p = atomicAdd(&g_cur[dst * N_RELS + r], 1);
        g_srcs[p] = src;
    }
}

// ---------------------------------------------------------------------------
// Fused aggregate+GEMM: out = X@root + sum_r mean_agg_r(X)@W[r] + bias (relu?)
// Per 64-node tile: seg 0 loads X rows; segs 1..8 gather-sum CSR sources for
// relation (seg-1) directly into the As smem tile, then FFMA against W.
template<int FOUT, bool RELU>
__global__ __launch_bounds__(256)
void gemm_fused_k(const float* __restrict__ X,      // [N,64]
                  const float* __restrict__ root,   // [64,FOUT]
                  const float* __restrict__ Wr,     // [R,64,FOUT]
                  const float* __restrict__ bias,   // [FOUT]
                  float* __restrict__ out)          // [N,FOUT]
{
    __shared__ float As[64 * 64];
    __shared__ float Ws[64 * FOUT];

    const int tid = threadIdx.x;
    const int tx = tid & 15;
    const int ty = tid >> 4;
    const int row0 = blockIdx.x * 64;
    constexpr int CJ = FOUT / 16;

    // gather role: 4 threads per tile-row, 16 floats each
    const int grow_g = row0 + (tid >> 2);   // tile row handled by this thread
    const int q = tid & 3;

    float acc[4][CJ];
    #pragma unroll
    for (int i = 0; i < 4; i++)
        #pragma unroll
        for (int j = 0; j < CJ; j++) acc[i][j] = 0.f;

    for (int seg = 0; seg < 9; seg++) {
        const float* W = (seg == 0) ? root : (Wr + (size_t)(seg - 1) * 64 * FOUT);

        // ---- build A tile ----
        if (seg == 0) {
            // plain load of X rows
            #pragma unroll
            for (int i = 0; i < 4; i++) {
                int lin = tid + i * 256;
                int r = lin >> 4, c4 = lin & 15;
                int grow = row0 + r;
                float4 v = make_float4(0.f, 0.f, 0.f, 0.f);
                if (grow < N_NODES) v = ((const float4*)(X + (size_t)grow * 64))[c4];
                ((float4*)As)[lin] = v;
            }
        } else {
            // CSR gather-sum for relation (seg-1)
            float4 s0 = make_float4(0.f, 0.f, 0.f, 0.f);
            float4 s1 = s0, s2 = s0, s3 = s0;
            float w = 0.f;
            if (grow_g < N_NODES) {
                int segid = grow_g * N_RELS + (seg - 1);
                int start = g_off[segid];
                int cnt = g_cnt[segid];
                w = g_inv[segid];
                for (int i = 0; i < cnt; i++) {
                    int src = g_srcs[start + i];
                    const float4* xp = (const float4*)(X + (size_t)src * 64) + q * 4;
                    float4 a = xp[0], b = xp[1], c = xp[2], d = xp[3];
                    s0.x += a.x; s0.y += a.y; s0.z += a.z; s0.w += a.w;
                    s1.x += b.x; s1.y += b.y; s1.z += b.z; s1.w += b.w;
                    s2.x += c.x; s2.y += c.y; s2.z += c.z; s2.w += c.w;
                    s3.x += d.x; s3.y += d.y; s3.z += d.z; s3.w += d.w;
                }
            }
            s0.x *= w; s0.y *= w; s0.z *= w; s0.w *= w;
            s1.x *= w; s1.y *= w; s1.z *= w; s1.w *= w;
            s2.x *= w; s2.y *= w; s2.z *= w; s2.w *= w;
            s3.x *= w; s3.y *= w; s3.z *= w; s3.w *= w;
            float4* ap = (float4*)(As + (size_t)(tid >> 2) * 64) + q * 4;
            ap[0] = s0; ap[1] = s1; ap[2] = s2; ap[3] = s3;
        }

        // ---- load W tile ----
        constexpr int WF4 = 64 * FOUT / 4;
        #pragma unroll
        for (int i = 0; i < WF4 / 256; i++) {
            int lin = tid + i * 256;
            ((float4*)Ws)[lin] = ((const float4*)W)[lin];
        }
        __syncthreads();

        // ---- FFMA ----
        #pragma unroll
        for (int k = 0; k < 64; k++) {
            float wv[CJ];
            #pragma unroll
            for (int j = 0; j < CJ; j++) wv[j] = Ws[k * FOUT + tx + 16 * j];
            #pragma unroll
            for (int i = 0; i < 4; i++) {
                float a = As[(ty + 16 * i) * 64 + k];
                #pragma unroll
                for (int j = 0; j < CJ; j++)
                    acc[i][j] = fmaf(a, wv[j], acc[i][j]);
            }
        }
        __syncthreads();
    }

    #pragma unroll
    for (int i = 0; i < 4; i++) {
        int grow = row0 + ty + 16 * i;
        if (grow < N_NODES) {
            #pragma unroll
            for (int j = 0; j < CJ; j++) {
                int c = tx + 16 * j;
                float v = acc[i][j] + bias[c];
                if (RELU) v = fmaxf(v, 0.f);
                out[(size_t)grow * FOUT + c] = v;
            }
        }
    }
}

// ---------------------------------------------------------------------------
extern "C" void kernel_launch(void* const* d_in, const int* in_sizes, int n_in,
                              void* d_out, int out_size) {
    const float* x     = (const float*)d_in[0];
    const int*   ei    = (const int*)d_in[1];   // int32 on device (JAX x64 off)
    const int*   et    = (const int*)d_in[2];
    const float* W1    = (const float*)d_in[3];
    const float* root1 = (const float*)d_in[4];
    const float* b1    = (const float*)d_in[5];
    const float* W2    = (const float*)d_in[6];
    const float* root2 = (const float*)d_in[7];
    const float* b2    = (const float*)d_in[8];
    float* out = (float*)d_out;

    float* h_ptr = nullptr;
    cudaGetSymbolAddress((void**)&h_ptr, g_h);

    const int segBlocks  = (NSEG + 255) / 256;
    const int edgeBlocks = (N_EDGES + 255) / 256;
    const int gemmBlocks = (N_NODES + 63) / 64;

    // CSR build (shared by both layers)
    zero_cnt_k<<<segBlocks, 256>>>();
    count_k<<<edgeBlocks, 256>>>(ei, et);
    inv_k<<<segBlocks, 256>>>();
    scan1_k<<<NCHUNK, 256>>>();
    scan2_k<<<1, 256>>>();
    scan3_k<<<segBlocks, 256>>>();
    fill_k<<<edgeBlocks, 256>>>(ei, et);

    // Layer 1 (fused aggregate + GEMM)
    gemm_fused_k<64, true><<<gemmBlocks, 256>>>(x, root1, W1, b1, h_ptr);

    // Layer 2
    gemm_fused_k<32, false><<<gemmBlocks, 256>>>(h_ptr, root2, W2, b2, out);
}

// round 7
// speedup vs baseline: 2.4513x; 1.0141x over previous
#include <cuda_runtime.h>

#define N_NODES 50000
#define N_EDGES 800000
#define N_RELS  8
#define NSEG    (N_NODES * N_RELS)       // 400000 segments, key = dst*8 + rel
#define SCAN_CHUNK 2048
#define NCHUNK  ((NSEG + SCAN_CHUNK - 1) / SCAN_CHUNK)   // 196

// Scratch (device globals; no allocation allowed anywhere)
__device__ float g_h[(size_t)N_NODES * 64];  // layer-1 output (post-ReLU)
__device__ int   g_cnt[NSEG];
__device__ float g_inv[NSEG];
__device__ int   g_off[NSEG];                // CSR segment start
__device__ int   g_cur[NSEG];                // fill cursors
__device__ int   g_bsum[NCHUNK];
__device__ int   g_srcs[N_EDGES];            // src ids sorted by segment

// ---------------------------------------------------------------------------
__global__ void zero_cnt_k() {
    int i = blockIdx.x * blockDim.x + threadIdx.x;
    if (i < NSEG) g_cnt[i] = 0;
}

__global__ void count_k(const int* __restrict__ ei,
                        const int* __restrict__ et) {
    int e = blockIdx.x * blockDim.x + threadIdx.x;
    if (e < N_EDGES) {
        int dst = ei[N_EDGES + e];
        int r   = et[e];
        atomicAdd(&g_cnt[dst * N_RELS + r], 1);
    }
}

__global__ void inv_k() {
    int i = blockIdx.x * blockDim.x + threadIdx.x;
    if (i < NSEG) {
        int c = g_cnt[i];
        g_inv[i] = 1.0f / (float)(c > 1 ? c : 1);
    }
}

// --- 3-phase exclusive scan of g_cnt -> g_off ------------------------------
__global__ void scan1_k() {  // grid NCHUNK, block 256; each thread 8 elems
    __shared__ int sh[256];
    int t = threadIdx.x;
    int base = blockIdx.x * SCAN_CHUNK + t * 8;
    int v[8]; int s = 0;
    #pragma unroll
    for (int i = 0; i < 8; i++) {
        int idx = base + i;
        v[i] = (idx < NSEG) ? g_cnt[idx] : 0;
        s += v[i];
    }
    sh[t] = s;
    __syncthreads();
    for (int off = 1; off < 256; off <<= 1) {
        int u = (t >= off) ? sh[t - off] : 0;
        __syncthreads();
        sh[t] += u;
        __syncthreads();
    }
    if (t == 255) g_bsum[blockIdx.x] = sh[255];
    int run = sh[t] - s;   // exclusive prefix of this thread's chunk
    #pragma unroll
    for (int i = 0; i < 8; i++) {
        if (base + i < NSEG) g_off[base + i] = run;
        run += v[i];
    }
}

__global__ void scan2_k() {  // 1 block, 256 threads; scans NCHUNK totals
    __shared__ int sh[256];
    int t = threadIdx.x;
    int s = (t < NCHUNK) ? g_bsum[t] : 0;
    sh[t] = s;
    __syncthreads();
    for (int off = 1; off < 256; off <<= 1) {
        int u = (t >= off) ? sh[t - off] : 0;
        __syncthreads();
        sh[t] += u;
        __syncthreads();
    }
    if (t < NCHUNK) g_bsum[t] = sh[t] - s;  // exclusive
}

__global__ void scan3_k() {  // finalize offsets + init cursors
    int i = blockIdx.x * blockDim.x + threadIdx.x;
    if (i < NSEG) {
        int o = g_off[i] + g_bsum[i >> 11];   // 2048 = 1<<11
        g_off[i] = o;
        g_cur[i] = o;
    }
}

__global__ void fill_k(const int* __restrict__ ei,
                       const int* __restrict__ et) {
    int e = blockIdx.x * blockDim.x + threadIdx.x;
    if (e < N_EDGES) {
        int src = ei[e];
        int dst = ei[N_EDGES + e];
        int r   = et[e];
        int p = atomicAdd(&g_cur[dst * N_RELS + r], 1);
        g_srcs[p] = src;
    }
}

// ---------------------------------------------------------------------------
// Fused aggregate+GEMM: out = X@root + sum_r mean_agg_r(X)@W[r] + bias (relu?)
// Columns per thread are CONTIGUOUS (tx*CJ .. tx*CJ+CJ-1) so W and output
// accesses vectorize. Inner loop unrolled by 4 over k with LDS.128.
template<int FOUT, bool RELU>
__global__ __launch_bounds__(256)
void gemm_fused_k(const float* __restrict__ X,      // [N,64]
                  const float* __restrict__ root,   // [64,FOUT]
                  const float* __restrict__ Wr,     // [R,64,FOUT]
                  const float* __restrict__ bias,   // [FOUT]
                  float* __restrict__ out)          // [N,FOUT]
{
    __shared__ float As[64 * 64];
    __shared__ float Ws[64 * FOUT];

    const int tid = threadIdx.x;
    const int tx = tid & 15;
    const int ty = tid >> 4;
    const int row0 = blockIdx.x * 64;
    constexpr int CJ = FOUT / 16;      // 4 or 2 contiguous columns per thread
    const int col0 = tx * CJ;

    // gather role: 4 threads per tile-row, 16 floats each
    const int rrow = tid >> 2;              // 0..63 tile row
    const int grow_g = row0 + rrow;
    const int q = tid & 3;

    // Prefetch CSR headers for this thread's gather row (8 rels, contiguous)
    int off8[8], cnt8[8];
    float inv8[8];
    if (grow_g < N_NODES) {
        const int4* op = (const int4*)(g_off + grow_g * N_RELS);
        const int4* cp = (const int4*)(g_cnt + grow_g * N_RELS);
        const float4* ip = (const float4*)(g_inv + grow_g * N_RELS);
        int4 o0 = op[0], o1 = op[1];
        int4 c0 = cp[0], c1 = cp[1];
        float4 i0 = ip[0], i1 = ip[1];
        off8[0]=o0.x; off8[1]=o0.y; off8[2]=o0.z; off8[3]=o0.w;
        off8[4]=o1.x; off8[5]=o1.y; off8[6]=o1.z; off8[7]=o1.w;
        cnt8[0]=c0.x; cnt8[1]=c0.y; cnt8[2]=c0.z; cnt8[3]=c0.w;
        cnt8[4]=c1.x; cnt8[5]=c1.y; cnt8[6]=c1.z; cnt8[7]=c1.w;
        inv8[0]=i0.x; inv8[1]=i0.y; inv8[2]=i0.z; inv8[3]=i0.w;
        inv8[4]=i1.x; inv8[5]=i1.y; inv8[6]=i1.z; inv8[7]=i1.w;
    } else {
        #pragma unroll
        for (int r = 0; r < 8; r++) { off8[r] = 0; cnt8[r] = 0; inv8[r] = 0.f; }
    }

    float acc[4][CJ];
    #pragma unroll
    for (int i = 0; i < 4; i++)
        #pragma unroll
        for (int j = 0; j < CJ; j++) acc[i][j] = 0.f;

    for (int seg = 0; seg < 9; seg++) {
        const float* W = (seg == 0) ? root : (Wr + (size_t)(seg - 1) * 64 * FOUT);

        // ---- build A tile ----
        if (seg == 0) {
            #pragma unroll
            for (int i = 0; i < 4; i++) {
                int lin = tid + i * 256;
                int r = lin >> 4, c4 = lin & 15;
                int grow = row0 + r;
                float4 v = make_float4(0.f, 0.f, 0.f, 0.f);
                if (grow < N_NODES) v = ((const float4*)(X + (size_t)grow * 64))[c4];
                ((float4*)As)[lin] = v;
            }
        } else {
            int rel = seg - 1;
            float4 s0 = make_float4(0.f, 0.f, 0.f, 0.f);
            float4 s1 = s0, s2 = s0, s3 = s0;
            int start = off8[rel];
            int cnt = cnt8[rel];
            float w = inv8[rel];
            for (int i = 0; i < cnt; i++) {
                int src = g_srcs[start + i];
                const float4* xp = (const float4*)(X + (size_t)src * 64) + q * 4;
                float4 a = xp[0], b = xp[1], c = xp[2], d = xp[3];
                s0.x += a.x; s0.y += a.y; s0.z += a.z; s0.w += a.w;
                s1.x += b.x; s1.y += b.y; s1.z += b.z; s1.w += b.w;
                s2.x += c.x; s2.y += c.y; s2.z += c.z; s2.w += c.w;
                s3.x += d.x; s3.y += d.y; s3.z += d.z; s3.w += d.w;
            }
            s0.x *= w; s0.y *= w; s0.z *= w; s0.w *= w;
            s1.x *= w; s1.y *= w; s1.z *= w; s1.w *= w;
            s2.x *= w; s2.y *= w; s2.z *= w; s2.w *= w;
            s3.x *= w; s3.y *= w; s3.z *= w; s3.w *= w;
            float4* ap = (float4*)(As + (size_t)rrow * 64) + q * 4;
            ap[0] = s0; ap[1] = s1; ap[2] = s2; ap[3] = s3;
        }

        // ---- load W tile ----
        constexpr int WF4 = 64 * FOUT / 4;
        #pragma unroll
        for (int i = 0; i < WF4 / 256; i++) {
            int lin = tid + i * 256;
            ((float4*)Ws)[lin] = ((const float4*)W)[lin];
        }
        __syncthreads();

        // ---- FFMA: k unrolled by 4, all smem traffic 128-bit ----
        #pragma unroll
        for (int k = 0; k < 64; k += 4) {
            float4 a4[4];
            #pragma unroll
            for (int i = 0; i < 4; i++)
                a4[i] = *(const float4*)&As[(ty + 16 * i) * 64 + k];
            #pragma unroll
            for (int kk = 0; kk < 4; kk++) {
                float av[4] = { a4[0].x, a4[1].x, a4[2].x, a4[3].x };
                if (kk == 1) { av[0]=a4[0].y; av[1]=a4[1].y; av[2]=a4[2].y; av[3]=a4[3].y; }
                if (kk == 2) { av[0]=a4[0].z; av[1]=a4[1].z; av[2]=a4[2].z; av[3]=a4[3].z; }
                if (kk == 3) { av[0]=a4[0].w; av[1]=a4[1].w; av[2]=a4[2].w; av[3]=a4[3].w; }
                if (CJ == 4) {
                    float4 wv = *(const float4*)&Ws[(k + kk) * FOUT + col0];
                    #pragma unroll
                    for (int i = 0; i < 4; i++) {
                        acc[i][0] = fmaf(av[i], wv.x, acc[i][0]);
                        acc[i][1] = fmaf(av[i], wv.y, acc[i][1]);
                        acc[i][2] = fmaf(av[i], wv.z, acc[i][2]);
                        acc[i][3] = fmaf(av[i], wv.w, acc[i][3]);
                    }
                } else {
                    float2 wv = *(const float2*)&Ws[(k + kk) * FOUT + col0];
                    #pragma unroll
                    for (int i = 0; i < 4; i++) {
                        acc[i][0] = fmaf(av[i], wv.x, acc[i][0]);
                        acc[i][1] = fmaf(av[i], wv.y, acc[i][1]);
                    }
                }
            }
        }
        __syncthreads();
    }

    // bias (vector load) + optional relu + vector store
    if (CJ == 4) {
        float4 bv = *(const float4*)&bias[col0];
        #pragma unroll
        for (int i = 0; i < 4; i++) {
            int grow = row0 + ty + 16 * i;
            if (grow < N_NODES) {
                float4 v = make_float4(acc[i][0] + bv.x, acc[i][1] + bv.y,
                                       acc[i][2] + bv.z, acc[i][3] + bv.w);
                if (RELU) {
                    v.x = fmaxf(v.x, 0.f); v.y = fmaxf(v.y, 0.f);
                    v.z = fmaxf(v.z, 0.f); v.w = fmaxf(v.w, 0.f);
                }
                *(float4*)&out[(size_t)grow * FOUT + col0] = v;
            }
        }
    } else {
        float2 bv = *(const float2*)&bias[col0];
        #pragma unroll
        for (int i = 0; i < 4; i++) {
            int grow = row0 + ty + 16 * i;
            if (grow < N_NODES) {
                float2 v = make_float2(acc[i][0] + bv.x, acc[i][1] + bv.y);
                if (RELU) { v.x = fmaxf(v.x, 0.f); v.y = fmaxf(v.y, 0.f); }
                *(float2*)&out[(size_t)grow * FOUT + col0] = v;
            }
        }
    }
}

// ---------------------------------------------------------------------------
extern "C" void kernel_launch(void* const* d_in, const int* in_sizes, int n_in,
                              void* d_out, int out_size) {
    const float* x     = (const float*)d_in[0];
    const int*   ei    = (const int*)d_in[1];   // int32 on device (JAX x64 off)
    const int*   et    = (const int*)d_in[2];
    const float* W1    = (const float*)d_in[3];
    const float* root1 = (const float*)d_in[4];
    const float* b1    = (const float*)d_in[5];
    const float* W2    = (const float*)d_in[6];
    const float* root2 = (const float*)d_in[7];
    const float* b2    = (const float*)d_in[8];
    float* out = (float*)d_out;

    float* h_ptr = nullptr;
    cudaGetSymbolAddress((void**)&h_ptr, g_h);

    const int segBlocks  = (NSEG + 255) / 256;
    const int edgeBlocks = (N_EDGES + 255) / 256;
    const int gemmBlocks = (N_NODES + 63) / 64;

    // CSR build (shared by both layers)
    zero_cnt_k<<<segBlocks, 256>>>();
    count_k<<<edgeBlocks, 256>>>(ei, et);
    inv_k<<<segBlocks, 256>>>();
    scan1_k<<<NCHUNK, 256>>>();
    scan2_k<<<1, 256>>>();
    scan3_k<<<segBlocks, 256>>>();
    fill_k<<<edgeBlocks, 256>>>(ei, et);

    // Layer 1 (fused aggregate + GEMM)
    gemm_fused_k<64, true><<<gemmBlocks, 256>>>(x, root1, W1, b1, h_ptr);

    // Layer 2
    gemm_fused_k<32, false><<<gemmBlocks, 256>>>(h_ptr, root2, W2, b2, out);
}

// round 8
// speedup vs baseline: 2.4891x; 1.0154x over previous
#include <cuda_runtime.h>

#define N_NODES 50000
#define N_EDGES 800000
#define N_RELS  8
#define NSEG    (N_NODES * N_RELS)       // 400000 segments, key = dst*8 + rel
#define SCAN_CHUNK 2048
#define NCHUNK  ((NSEG + SCAN_CHUNK - 1) / SCAN_CHUNK)   // 196

// Scratch (device globals; no allocation allowed anywhere)
__device__ float g_h[(size_t)N_NODES * 64];  // layer-1 output (post-ReLU)
__device__ int   g_cnt[NSEG];
__device__ float g_inv[NSEG];
__device__ int   g_off[NSEG];                // CSR segment start
__device__ int   g_cur[NSEG];                // fill cursors
__device__ int   g_bsum[NCHUNK];
__device__ int   g_srcs[N_EDGES];            // src ids sorted by segment

// ---------------------------------------------------------------------------
__global__ void zero_cnt_k() {
    int i = blockIdx.x * blockDim.x + threadIdx.x;
    if (i < NSEG) g_cnt[i] = 0;
}

__global__ void count_k(const int* __restrict__ ei,
                        const int* __restrict__ et) {
    int e = blockIdx.x * blockDim.x + threadIdx.x;
    if (e < N_EDGES) {
        int dst = ei[N_EDGES + e];
        int r   = et[e];
        atomicAdd(&g_cnt[dst * N_RELS + r], 1);
    }
}

__global__ void inv_k() {
    int i = blockIdx.x * blockDim.x + threadIdx.x;
    if (i < NSEG) {
        int c = g_cnt[i];
        g_inv[i] = 1.0f / (float)(c > 1 ? c : 1);
    }
}

// --- 3-phase exclusive scan of g_cnt -> g_off ------------------------------
__global__ void scan1_k() {  // grid NCHUNK, block 256; each thread 8 elems
    __shared__ int sh[256];
    int t = threadIdx.x;
    int base = blockIdx.x * SCAN_CHUNK + t * 8;
    int v[8]; int s = 0;
    #pragma unroll
    for (int i = 0; i < 8; i++) {
        int idx = base + i;
        v[i] = (idx < NSEG) ? g_cnt[idx] : 0;
        s += v[i];
    }
    sh[t] = s;
    __syncthreads();
    for (int off = 1; off < 256; off <<= 1) {
        int u = (t >= off) ? sh[t - off] : 0;
        __syncthreads();
        sh[t] += u;
        __syncthreads();
    }
    if (t == 255) g_bsum[blockIdx.x] = sh[255];
    int run = sh[t] - s;   // exclusive prefix of this thread's chunk
    #pragma unroll
    for (int i = 0; i < 8; i++) {
        if (base + i < NSEG) g_off[base + i] = run;
        run += v[i];
    }
}

__global__ void scan2_k() {  // 1 block, 256 threads; scans NCHUNK totals
    __shared__ int sh[256];
    int t = threadIdx.x;
    int s = (t < NCHUNK) ? g_bsum[t] : 0;
    sh[t] = s;
    __syncthreads();
    for (int off = 1; off < 256; off <<= 1) {
        int u = (t >= off) ? sh[t - off] : 0;
        __syncthreads();
        sh[t] += u;
        __syncthreads();
    }
    if (t < NCHUNK) g_bsum[t] = sh[t] - s;  // exclusive
}

__global__ void scan3_k() {  // finalize offsets + init cursors
    int i = blockIdx.x * blockDim.x + threadIdx.x;
    if (i < NSEG) {
        int o = g_off[i] + g_bsum[i >> 11];   // 2048 = 1<<11
        g_off[i] = o;
        g_cur[i] = o;
    }
}

__global__ void fill_k(const int* __restrict__ ei,
                       const int* __restrict__ et) {
    int e = blockIdx.x * blockDim.x + threadIdx.x;
    if (e < N_EDGES) {
        int src = ei[e];
        int dst = ei[N_EDGES + e];
        int r   = et[e];
        int p = atomicAdd(&g_cur[dst * N_RELS + r], 1);
        g_srcs[p] = src;
    }
}

// ---------------------------------------------------------------------------
// Fused aggregate+GEMM, software-pipelined: double-buffered A and W tiles;
// gather of segment s+1 overlaps FFMA of segment s. One barrier per segment.
template<int FOUT, bool RELU>
__global__ __launch_bounds__(256)
void gemm_fused_k(const float* __restrict__ X,      // [N,64]
                  const float* __restrict__ root,   // [64,FOUT]
                  const float* __restrict__ Wr,     // [R,64,FOUT]
                  const float* __restrict__ bias,   // [FOUT]
                  float* __restrict__ out)          // [N,FOUT]
{
    __shared__ float As[2][64 * 64];
    __shared__ float Ws[2][64 * FOUT];

    const int tid = threadIdx.x;
    const int tx = tid & 15;
    const int ty = tid >> 4;
    const int row0 = blockIdx.x * 64;
    constexpr int CJ = FOUT / 16;      // 4 or 2 contiguous columns per thread
    const int col0 = tx * CJ;

    // gather role: 4 threads per tile-row, 16 floats each
    const int rrow = tid >> 2;              // 0..63 tile row
    const int grow_g = row0 + rrow;
    const int q = tid & 3;

    // Prefetch CSR headers for this thread's gather row (8 rels, contiguous)
    int off8[8], cnt8[8];
    float inv8[8];
    if (grow_g < N_NODES) {
        const int4* op = (const int4*)(g_off + grow_g * N_RELS);
        const int4* cp = (const int4*)(g_cnt + grow_g * N_RELS);
        const float4* ip = (const float4*)(g_inv + grow_g * N_RELS);
        int4 o0 = op[0], o1 = op[1];
        int4 c0 = cp[0], c1 = cp[1];
        float4 i0 = ip[0], i1 = ip[1];
        off8[0]=o0.x; off8[1]=o0.y; off8[2]=o0.z; off8[3]=o0.w;
        off8[4]=o1.x; off8[5]=o1.y; off8[6]=o1.z; off8[7]=o1.w;
        cnt8[0]=c0.x; cnt8[1]=c0.y; cnt8[2]=c0.z; cnt8[3]=c0.w;
        cnt8[4]=c1.x; cnt8[5]=c1.y; cnt8[6]=c1.z; cnt8[7]=c1.w;
        inv8[0]=i0.x; inv8[1]=i0.y; inv8[2]=i0.z; inv8[3]=i0.w;
        inv8[4]=i1.x; inv8[5]=i1.y; inv8[6]=i1.z; inv8[7]=i1.w;
    } else {
        #pragma unroll
        for (int r = 0; r < 8; r++) { off8[r] = 0; cnt8[r] = 0; inv8[r] = 0.f; }
    }

    float acc[4][CJ];
    #pragma unroll
    for (int i = 0; i < 4; i++)
        #pragma unroll
        for (int j = 0; j < CJ; j++) acc[i][j] = 0.f;

    constexpr int WF4 = 64 * FOUT / 4;

    // ---- prologue: segment 0 = X rows into As[0], root into Ws[0] ----
    #pragma unroll
    for (int i = 0; i < 4; i++) {
        int lin = tid + i * 256;
        int r = lin >> 4, c4 = lin & 15;
        int grow = row0 + r;
        float4 v = make_float4(0.f, 0.f, 0.f, 0.f);
        if (grow < N_NODES) v = ((const float4*)(X + (size_t)grow * 64))[c4];
        ((float4*)As[0])[lin] = v;
    }
    #pragma unroll
    for (int i = 0; i < WF4 / 256; i++) {
        int lin = tid + i * 256;
        ((float4*)Ws[0])[lin] = ((const float4*)root)[lin];
    }
    __syncthreads();

    for (int seg = 0; seg < 9; seg++) {
        const int b = seg & 1;

        // ---- produce segment seg+1 into buffer b^1 (overlaps FFMA below) ----
        if (seg < 8) {
            const int rel = seg;
            float4 s0 = make_float4(0.f, 0.f, 0.f, 0.f);
            float4 s1 = s0, s2 = s0, s3 = s0;
            int start = off8[rel];
            int cnt = cnt8[rel];
            float w = inv8[rel];
            for (int i = 0; i < cnt; i++) {
                int src = g_srcs[start + i];
                const float4* xp = (const float4*)(X + (size_t)src * 64) + q * 4;
                float4 a = xp[0], bb = xp[1], c = xp[2], d = xp[3];
                s0.x += a.x;  s0.y += a.y;  s0.z += a.z;  s0.w += a.w;
                s1.x += bb.x; s1.y += bb.y; s1.z += bb.z; s1.w += bb.w;
                s2.x += c.x;  s2.y += c.y;  s2.z += c.z;  s2.w += c.w;
                s3.x += d.x;  s3.y += d.y;  s3.z += d.z;  s3.w += d.w;
            }
            s0.x *= w; s0.y *= w; s0.z *= w; s0.w *= w;
            s1.x *= w; s1.y *= w; s1.z *= w; s1.w *= w;
            s2.x *= w; s2.y *= w; s2.z *= w; s2.w *= w;
            s3.x *= w; s3.y *= w; s3.z *= w; s3.w *= w;
            float4* ap = (float4*)(As[b ^ 1] + (size_t)rrow * 64) + q * 4;
            ap[0] = s0; ap[1] = s1; ap[2] = s2; ap[3] = s3;

            const float* W = Wr + (size_t)rel * 64 * FOUT;
            #pragma unroll
            for (int i = 0; i < WF4 / 256; i++) {
                int lin = tid + i * 256;
                ((float4*)Ws[b ^ 1])[lin] = ((const float4*)W)[lin];
            }
        }

        // ---- FFMA segment seg from buffer b ----
        const float* Asb = As[b];
        const float* Wsb = Ws[b];
        #pragma unroll
        for (int k = 0; k < 64; k += 4) {
            float4 a4[4];
            #pragma unroll
            for (int i = 0; i < 4; i++)
                a4[i] = *(const float4*)&Asb[(ty + 16 * i) * 64 + k];
            #pragma unroll
            for (int kk = 0; kk < 4; kk++) {
                float av[4] = { a4[0].x, a4[1].x, a4[2].x, a4[3].x };
                if (kk == 1) { av[0]=a4[0].y; av[1]=a4[1].y; av[2]=a4[2].y; av[3]=a4[3].y; }
                if (kk == 2) { av[0]=a4[0].z; av[1]=a4[1].z; av[2]=a4[2].z; av[3]=a4[3].z; }
                if (kk == 3) { av[0]=a4[0].w; av[1]=a4[1].w; av[2]=a4[2].w; av[3]=a4[3].w; }
                if (CJ == 4) {
                    float4 wv = *(const float4*)&Wsb[(k + kk) * FOUT + col0];
                    #pragma unroll
                    for (int i = 0; i < 4; i++) {
                        acc[i][0] = fmaf(av[i], wv.x, acc[i][0]);
                        acc[i][1] = fmaf(av[i], wv.y, acc[i][1]);
                        acc[i][2] = fmaf(av[i], wv.z, acc[i][2]);
                        acc[i][3] = fmaf(av[i], wv.w, acc[i][3]);
                    }
                } else {
                    float2 wv = *(const float2*)&Wsb[(k + kk) * FOUT + col0];
                    #pragma unroll
                    for (int i = 0; i < 4; i++) {
                        acc[i][0] = fmaf(av[i], wv.x, acc[i][0]);
                        acc[i][1] = fmaf(av[i], wv.y, acc[i][1]);
                    }
                }
            }
        }
        __syncthreads();
    }

    // bias (vector load) + optional relu + vector store
    if (CJ == 4) {
        float4 bv = *(const float4*)&bias[col0];
        #pragma unroll
        for (int i = 0; i < 4; i++) {
            int grow = row0 + ty + 16 * i;
            if (grow < N_NODES) {
                float4 v = make_float4(acc[i][0] + bv.x, acc[i][1] + bv.y,
                                       acc[i][2] + bv.z, acc[i][3] + bv.w);
                if (RELU) {
                    v.x = fmaxf(v.x, 0.f); v.y = fmaxf(v.y, 0.f);
                    v.z = fmaxf(v.z, 0.f); v.w = fmaxf(v.w, 0.f);
                }
                *(float4*)&out[(size_t)grow * FOUT + col0] = v;
            }
        }
    } else {
        float2 bv = *(const float2*)&bias[col0];
        #pragma unroll
        for (int i = 0; i < 4; i++) {
            int grow = row0 + ty + 16 * i;
            if (grow < N_NODES) {
                float2 v = make_float2(acc[i][0] + bv.x, acc[i][1] + bv.y);
                if (RELU) { v.x = fmaxf(v.x, 0.f); v.y = fmaxf(v.y, 0.f); }
                *(float2*)&out[(size_t)grow * FOUT + col0] = v;
            }
        }
    }
}

// ---------------------------------------------------------------------------
extern "C" void kernel_launch(void* const* d_in, const int* in_sizes, int n_in,
                              void* d_out, int out_size) {
    const float* x     = (const float*)d_in[0];
    const int*   ei    = (const int*)d_in[1];   // int32 on device (JAX x64 off)
    const int*   et    = (const int*)d_in[2];
    const float* W1    = (const float*)d_in[3];
    const float* root1 = (const float*)d_in[4];
    const float* b1    = (const float*)d_in[5];
    const float* W2    = (const float*)d_in[6];
    const float* root2 = (const float*)d_in[7];
    const float* b2    = (const float*)d_in[8];
    float* out = (float*)d_out;

    float* h_ptr = nullptr;
    cudaGetSymbolAddress((void**)&h_ptr, g_h);

    const int segBlocks  = (NSEG + 255) / 256;
    const int edgeBlocks = (N_EDGES + 255) / 256;
    const int gemmBlocks = (N_NODES + 63) / 64;

    // CSR build (shared by both layers)
    zero_cnt_k<<<segBlocks, 256>>>();
    count_k<<<edgeBlocks, 256>>>(ei, et);
    inv_k<<<segBlocks, 256>>>();
    scan1_k<<<NCHUNK, 256>>>();
    scan2_k<<<1, 256>>>();
    scan3_k<<<segBlocks, 256>>>();
    fill_k<<<edgeBlocks, 256>>>(ei, et);

    // Layer 1 (fused aggregate + GEMM, pipelined)
    gemm_fused_k<64, true><<<gemmBlocks, 256>>>(x, root1, W1, b1, h_ptr);

    // Layer 2
    gemm_fused_k<32, false><<<gemmBlocks, 256>>>(h_ptr, root2, W2, b2, out);
}

// round 10
// speedup vs baseline: 3.5754x; 1.4365x over previous
#include <cuda_runtime.h>
#include <cuda_bf16.h>

#define N_NODES 50000
#define N_EDGES 800000
#define N_RELS  8
#define NSEG    (N_NODES * N_RELS)
#define SCAN_CHUNK 2048
#define NCHUNK  ((NSEG + SCAN_CHUNK - 1) / SCAN_CHUNK)   // 196

// Scratch (device globals; no allocation allowed anywhere)
__device__ float g_h[(size_t)N_NODES * 64];
__device__ int   g_cnt[NSEG];
__device__ float g_inv[NSEG];
__device__ int   g_off[NSEG];
__device__ int   g_cur[NSEG];
__device__ int   g_bsum[NCHUNK];
__device__ int   g_srcs[N_EDGES];
// Pre-split weights, layout [seg][n][k] (n-major, k contiguous), bf16
__device__ __nv_bfloat16 g_B1h[9 * 64 * 64];
__device__ __nv_bfloat16 g_B1l[9 * 64 * 64];
__device__ __nv_bfloat16 g_B2h[9 * 32 * 64];
__device__ __nv_bfloat16 g_B2l[9 * 32 * 64];

// ============================ CSR build ====================================
__global__ void zero_cnt_k() {
    int i = blockIdx.x * blockDim.x + threadIdx.x;
    if (i < NSEG) g_cnt[i] = 0;
}

__global__ void count_k(const int* __restrict__ ei,
                        const int* __restrict__ et) {
    int e = blockIdx.x * blockDim.x + threadIdx.x;
    if (e < N_EDGES) {
        int dst = ei[N_EDGES + e];
        int r   = et[e];
        atomicAdd(&g_cnt[dst * N_RELS + r], 1);
    }
}

__global__ void inv_k() {
    int i = blockIdx.x * blockDim.x + threadIdx.x;
    if (i < NSEG) {
        int c = g_cnt[i];
        g_inv[i] = 1.0f / (float)(c > 1 ? c : 1);
    }
}

__global__ void scan1_k() {
    __shared__ int sh[256];
    int t = threadIdx.x;
    int base = blockIdx.x * SCAN_CHUNK + t * 8;
    int v[8]; int s = 0;
    #pragma unroll
    for (int i = 0; i < 8; i++) {
        int idx = base + i;
        v[i] = (idx < NSEG) ? g_cnt[idx] : 0;
        s += v[i];
    }
    sh[t] = s;
    __syncthreads();
    for (int off = 1; off < 256; off <<= 1) {
        int u = (t >= off) ? sh[t - off] : 0;
        __syncthreads();
        sh[t] += u;
        __syncthreads();
    }
    if (t == 255) g_bsum[blockIdx.x] = sh[255];
    int run = sh[t] - s;
    #pragma unroll
    for (int i = 0; i < 8; i++) {
        if (base + i < NSEG) g_off[base + i] = run;
        run += v[i];
    }
}

__global__ void scan2_k() {
    __shared__ int sh[256];
    int t = threadIdx.x;
    int s = (t < NCHUNK) ? g_bsum[t] : 0;
    sh[t] = s;
    __syncthreads();
    for (int off = 1; off < 256; off <<= 1) {
        int u = (t >= off) ? sh[t - off] : 0;
        __syncthreads();
        sh[t] += u;
        __syncthreads();
    }
    if (t < NCHUNK) g_bsum[t] = sh[t] - s;
}

__global__ void scan3_k() {
    int i = blockIdx.x * blockDim.x + threadIdx.x;
    if (i < NSEG) {
        int o = g_off[i] + g_bsum[i >> 11];
        g_off[i] = o;
        g_cur[i] = o;
    }
}

__global__ void fill_k(const int* __restrict__ ei,
                       const int* __restrict__ et) {
    int e = blockIdx.x * blockDim.x + threadIdx.x;
    if (e < N_EDGES) {
        int src = ei[e];
        int dst = ei[N_EDGES + e];
        int r   = et[e];
        int p = atomicAdd(&g_cur[dst * N_RELS + r], 1);
        g_srcs[p] = src;
    }
}

// ---- Weight transpose + bf16 split: [k][n] fp32 -> [seg][n][k] bf16 hi/lo --
__global__ void wconv_k(const float* __restrict__ root,
                        const float* __restrict__ Wr,
                        __nv_bfloat16* __restrict__ bh,
                        __nv_bfloat16* __restrict__ bl,
                        int fout) {
    int i = blockIdx.x * blockDim.x + threadIdx.x;
    int tot = 9 * fout * 64;
    if (i >= tot) return;
    int k = i & 63;
    int n = (i >> 6) % fout;
    int s = i / (64 * fout);
    float w = (s == 0) ? root[k * fout + n]
                       : Wr[((size_t)(s - 1) * 64 + k) * fout + n];
    __nv_bfloat16 h = __float2bfloat16(w);
    float lo = w - __bfloat162float(h);
    bh[i] = h;
    bl[i] = __float2bfloat16(lo);
}

// ============================ mma helpers ==================================
__device__ __forceinline__ unsigned smem_u32(const void* p) {
    unsigned a;
    asm("{ .reg .u64 t; cvta.to.shared.u64 t, %1; cvt.u32.u64 %0, t; }"
        : "=r"(a) : "l"(p));
    return a;
}

__device__ __forceinline__ void ldsm4(unsigned& r0, unsigned& r1,
                                      unsigned& r2, unsigned& r3, unsigned a) {
    asm volatile("ldmatrix.sync.aligned.m8n8.x4.shared.b16 {%0,%1,%2,%3}, [%4];"
                 : "=r"(r0), "=r"(r1), "=r"(r2), "=r"(r3) : "r"(a));
}

__device__ __forceinline__ void mma_bf16(float* c, const unsigned* a,
                                         unsigned b0, unsigned b1) {
    asm volatile(
        "mma.sync.aligned.m16n8k16.row.col.f32.bf16.bf16.f32 "
        "{%0,%1,%2,%3}, {%4,%5,%6,%7}, {%8,%9}, {%0,%1,%2,%3};"
        : "+f"(c[0]), "+f"(c[1]), "+f"(c[2]), "+f"(c[3])
        : "r"(a[0]), "r"(a[1]), "r"(a[2]), "r"(a[3]), "r"(b0), "r"(b1));
}

// split 16 fp32 -> bf16 hi/lo (two uint4 each)
__device__ __forceinline__ void split16(const float* v, uint4* hp, uint4* lp) {
    unsigned h[8], l[8];
    #pragma unroll
    for (int j = 0; j < 8; j++) {
        float a = v[2 * j], b = v[2 * j + 1];
        __nv_bfloat16 ha = __float2bfloat16(a);
        __nv_bfloat16 hb = __float2bfloat16(b);
        __nv_bfloat162 hh; hh.x = ha; hh.y = hb;
        __nv_bfloat162 ll;
        ll.x = __float2bfloat16(a - __bfloat162float(ha));
        ll.y = __float2bfloat16(b - __bfloat162float(hb));
        h[j] = *reinterpret_cast<unsigned*>(&hh);
        l[j] = *reinterpret_cast<unsigned*>(&ll);
    }
    hp[0] = make_uint4(h[0], h[1], h[2], h[3]);
    hp[1] = make_uint4(h[4], h[5], h[6], h[7]);
    lp[0] = make_uint4(l[0], l[1], l[2], l[3]);
    lp[1] = make_uint4(l[4], l[5], l[6], l[7]);
}

// ============================ fused gather + mma GEMM ======================
// Tile: 64 rows x FOUT cols, 256 threads (8 warps as 4x2).
// 9 segments of K=64; A built by CSR gather (split bf16), B copied from
// preconverted globals. Double buffered, one barrier per segment.
// Row stride 72 bf16 (144B) -> LDSM conflict-free.
#define ASTRB 144
template<int FOUT, bool RELU>
__global__ __launch_bounds__(256, 2)
void rgcn_mma_k(const float* __restrict__ X,
                const __nv_bfloat16* __restrict__ Bh,   // [9][FOUT][64]
                const __nv_bfloat16* __restrict__ Bl,
                const float* __restrict__ bias,
                float* __restrict__ out) {
    extern __shared__ char smem[];
    constexpr int APART = 64 * ASTRB;          // 9216 B
    constexpr int BPART = FOUT * ASTRB;
    // layout: Ahi0, Alo0, Ahi1, Alo1, Bhi0, Blo0, Bhi1, Blo1
    constexpr int OFF_B = 4 * APART;

    const int tid = threadIdx.x;
    const int wid = tid >> 5;
    const int lane = tid & 31;
    const int row0 = blockIdx.x * 64;
    const unsigned sb = smem_u32(smem);

    // gather role: 4 threads per row, 16 floats each
    const int rrow = tid >> 2;
    const int q = tid & 3;
    const int grow = row0 + rrow;

    int off8[8], cnt8[8];
    float inv8[8];
    if (grow < N_NODES) {
        const int4* op = (const int4*)(g_off + grow * N_RELS);
        const int4* cp = (const int4*)(g_cnt + grow * N_RELS);
        const float4* ip = (const float4*)(g_inv + grow * N_RELS);
        int4 o0 = op[0], o1 = op[1];
        int4 c0 = cp[0], c1 = cp[1];
        float4 i0 = ip[0], i1 = ip[1];
        off8[0]=o0.x; off8[1]=o0.y; off8[2]=o0.z; off8[3]=o0.w;
        off8[4]=o1.x; off8[5]=o1.y; off8[6]=o1.z; off8[7]=o1.w;
        cnt8[0]=c0.x; cnt8[1]=c0.y; cnt8[2]=c0.z; cnt8[3]=c0.w;
        cnt8[4]=c1.x; cnt8[5]=c1.y; cnt8[6]=c1.z; cnt8[7]=c1.w;
        inv8[0]=i0.x; inv8[1]=i0.y; inv8[2]=i0.z; inv8[3]=i0.w;
        inv8[4]=i1.x; inv8[5]=i1.y; inv8[6]=i1.z; inv8[7]=i1.w;
    } else {
        #pragma unroll
        for (int r = 0; r < 8; r++) { off8[r] = 0; cnt8[r] = 0; inv8[r] = 0.f; }
    }

    auto produce = [&](int s, int buf) {
        // ---- A: gather (seg 0 = identity), split, store ----
        float v[16];
        if (s == 0) {
            if (grow < N_NODES) {
                const float4* xp = (const float4*)(X + (size_t)grow * 64) + q * 4;
                #pragma unroll
                for (int i = 0; i < 4; i++) {
                    float4 t = xp[i];
                    v[4*i] = t.x; v[4*i+1] = t.y; v[4*i+2] = t.z; v[4*i+3] = t.w;
                }
            } else {
                #pragma unroll
                for (int i = 0; i < 16; i++) v[i] = 0.f;
            }
        } else {
            #pragma unroll
            for (int i = 0; i < 16; i++) v[i] = 0.f;
            int rel = s - 1;
            int start = off8[rel], cnt = cnt8[rel];
            float w = inv8[rel];
            for (int i = 0; i < cnt; i++) {
                int src = g_srcs[start + i];
                const float4* xp = (const float4*)(X + (size_t)src * 64) + q * 4;
                #pragma unroll
                for (int j = 0; j < 4; j++) {
                    float4 t = xp[j];
                    v[4*j] += t.x; v[4*j+1] += t.y; v[4*j+2] += t.z; v[4*j+3] += t.w;
                }
            }
            #pragma unroll
            for (int i = 0; i < 16; i++) v[i] *= w;
        }
        uint4 hp[2], lp[2];
        split16(v, hp, lp);
        char* Ahi = smem + (2 * buf + 0) * APART;
        char* Alo = smem + (2 * buf + 1) * APART;
        unsigned o = rrow * ASTRB + q * 32;
        *(uint4*)(Ahi + o) = hp[0];
        *(uint4*)(Ahi + o + 16) = hp[1];
        *(uint4*)(Alo + o) = lp[0];
        *(uint4*)(Alo + o + 16) = lp[1];

        // ---- B: copy preconverted [FOUT][64] bf16 rows (8 uint4 per row) ----
        char* Bhs = smem + OFF_B + (2 * buf + 0) * BPART;
        char* Bls = smem + OFF_B + (2 * buf + 1) * BPART;
        const uint4* sh = (const uint4*)(Bh + (size_t)s * FOUT * 64);
        const uint4* sl = (const uint4*)(Bl + (size_t)s * FOUT * 64);
        #pragma unroll
        for (int i = 0; i < FOUT / 32; i++) {
            int lin = tid + i * 256;
            int n = lin >> 3, c = lin & 7;
            unsigned d = n * ASTRB + c * 16;
            *(uint4*)(Bhs + d) = sh[lin];
            *(uint4*)(Bls + d) = sl[lin];
        }
    };

    // warp tile: 16 rows x (FOUT/2) cols
    const int warpRow = wid & 3;
    const int warpCol = wid >> 2;
    constexpr int NT = FOUT / 16;        // n-tiles (8 cols each): 4 or 2
    float c[NT][4];
    #pragma unroll
    for (int t = 0; t < NT; t++)
        #pragma unroll
        for (int j = 0; j < 4; j++) c[t][j] = 0.f;

    // ldmatrix lane addressing (x4: m = L/8; row += (m&1)*8; koff = (m>>1)*16)
    const int lrow = (lane & 7) + ((lane >> 3) & 1) * 8;
    const unsigned lkoff = (lane >> 4) * 16;

    produce(0, 0);
    __syncthreads();

    for (int seg = 0; seg < 9; seg++) {
        const int b = seg & 1;
        if (seg < 8) produce(seg + 1, b ^ 1);

        const unsigned Ahi = sb + (2 * b + 0) * APART;
        const unsigned Alo = sb + (2 * b + 1) * APART;
        const unsigned Bhi = sb + OFF_B + (2 * b + 0) * BPART;
        const unsigned Blo = sb + OFF_B + (2 * b + 1) * BPART;
        const unsigned aoff = (warpRow * 16 + lrow) * ASTRB + lkoff;

        #pragma unroll
        for (int kc = 0; kc < 4; kc++) {
            unsigned ah[4], al[4];
            ldsm4(ah[0], ah[1], ah[2], ah[3], Ahi + aoff + kc * 32);
            ldsm4(al[0], al[1], al[2], al[3], Alo + aoff + kc * 32);
            #pragma unroll
            for (int p = 0; p < NT / 2; p++) {
                unsigned boff = (warpCol * (FOUT / 2) + p * 16 + lrow) * ASTRB
                              + lkoff + kc * 32;
                unsigned bh0, bh1, bh2, bh3, bl0, bl1, bl2, bl3;
                ldsm4(bh0, bh1, bh2, bh3, Bhi + boff);
                ldsm4(bl0, bl1, bl2, bl3, Blo + boff);
                // regs: r0=(n0-7,k0-7) r1=(n8-15,k0-7) r2=(n0-7,k8-15) r3=(n8-15,k8-15)
                // tile 2p   = {r0, r2}; tile 2p+1 = {r1, r3}
                mma_bf16(c[2*p],     ah, bh0, bh2);
                mma_bf16(c[2*p],     ah, bl0, bl2);
                mma_bf16(c[2*p],     al, bh0, bh2);
                mma_bf16(c[2*p + 1], ah, bh1, bh3);
                mma_bf16(c[2*p + 1], ah, bl1, bl3);
                mma_bf16(c[2*p + 1], al, bh1, bh3);
            }
        }
        __syncthreads();
    }

    // epilogue: C fragment rows = lane/4 (+8), cols = tile*8 + (lane%4)*2
    const int er = row0 + warpRow * 16 + (lane >> 2);
    #pragma unroll
    for (int t = 0; t < NT; t++) {
        int cc = warpCol * (FOUT / 2) + t * 8 + (lane & 3) * 2;
        float2 bv = *(const float2*)&bias[cc];
        if (er < N_NODES) {
            float2 o = make_float2(c[t][0] + bv.x, c[t][1] + bv.y);
            if (RELU) { o.x = fmaxf(o.x, 0.f); o.y = fmaxf(o.y, 0.f); }
            *(float2*)&out[(size_t)er * FOUT + cc] = o;
        }
        if (er + 8 < N_NODES) {
            float2 o = make_float2(c[t][2] + bv.x, c[t][3] + bv.y);
            if (RELU) { o.x = fmaxf(o.x, 0.f); o.y = fmaxf(o.y, 0.f); }
            *(float2*)&out[(size_t)(er + 8) * FOUT + cc] = o;
        }
    }
}

// ---------------------------------------------------------------------------
extern "C" void kernel_launch(void* const* d_in, const int* in_sizes, int n_in,
                              void* d_out, int out_size) {
    const float* x     = (const float*)d_in[0];
    const int*   ei    = (const int*)d_in[1];   // int32 on device (JAX x64 off)
    const int*   et    = (const int*)d_in[2];
    const float* W1    = (const float*)d_in[3];
    const float* root1 = (const float*)d_in[4];
    const float* b1    = (const float*)d_in[5];
    const float* W2    = (const float*)d_in[6];
    const float* root2 = (const float*)d_in[7];
    const float* b2    = (const float*)d_in[8];
    float* out = (float*)d_out;

    float* h_ptr = nullptr;
    cudaGetSymbolAddress((void**)&h_ptr, g_h);
    __nv_bfloat16 *b1h, *b1l, *b2h, *b2l;
    cudaGetSymbolAddress((void**)&b1h, g_B1h);
    cudaGetSymbolAddress((void**)&b1l, g_B1l);
    cudaGetSymbolAddress((void**)&b2h, g_B2h);
    cudaGetSymbolAddress((void**)&b2l, g_B2l);

    constexpr int SMEM1 = 4 * 64 * ASTRB + 4 * 64 * ASTRB;  // 73728
    constexpr int SMEM2 = 4 * 64 * ASTRB + 4 * 32 * ASTRB;  // 55296
    cudaFuncSetAttribute(rgcn_mma_k<64, true>,
                         cudaFuncAttributeMaxDynamicSharedMemorySize, SMEM1);
    cudaFuncSetAttribute(rgcn_mma_k<32, false>,
                         cudaFuncAttributeMaxDynamicSharedMemorySize, SMEM2);

    const int segBlocks  = (NSEG + 255) / 256;
    const int edgeBlocks = (N_EDGES + 255) / 256;
    const int mmaBlocks  = (N_NODES + 63) / 64;

    // CSR build (shared by both layers) + weight preconversion
    zero_cnt_k<<<segBlocks, 256>>>();
    count_k<<<edgeBlocks, 256>>>(ei, et);
    inv_k<<<segBlocks, 256>>>();
    scan1_k<<<NCHUNK, 256>>>();
    scan2_k<<<1, 256>>>();
    scan3_k<<<segBlocks, 256>>>();
    fill_k<<<edgeBlocks, 256>>>(ei, et);
    wconv_k<<<(9 * 64 * 64 + 255) / 256, 256>>>(root1, W1, b1h, b1l, 64);
    wconv_k<<<(9 * 32 * 64 + 255) / 256, 256>>>(root2, W2, b2h, b2l, 32);

    // Layer 1 (fused gather + split-bf16 mma.sync GEMM)
    rgcn_mma_k<64, true><<<mmaBlocks, 256, SMEM1>>>(x, b1h, b1l, b1, h_ptr);

    // Layer 2
    rgcn_mma_k<32, false><<<mmaBlocks, 256, SMEM2>>>(h_ptr, b2h, b2l, b2, out);
}

// round 11
// speedup vs baseline: 4.1675x; 1.1656x over previous
#include <cuda_runtime.h>
#include <cuda_bf16.h>

#define N_NODES 50000
#define N_EDGES 800000
#define N_RELS  8
#define NSEG    (N_NODES * N_RELS)
#define SCAN_CHUNK 2048
#define NCHUNK  ((NSEG + SCAN_CHUNK - 1) / SCAN_CHUNK)   // 196

// Scratch (device globals; no allocation allowed anywhere)
__device__ float g_h[(size_t)N_NODES * 64];
__device__ int   g_cnt[NSEG];
__device__ float g_inv[NSEG];
__device__ int   g_off[NSEG];
__device__ int   g_cur[NSEG];
__device__ int   g_bsum[NCHUNK];
__device__ int   g_srcs[N_EDGES];
// Pre-split weights, layout [seg][n][k] (n-major, k contiguous), bf16
__device__ __nv_bfloat16 g_B1h[9 * 64 * 64];
__device__ __nv_bfloat16 g_B1l[9 * 64 * 64];
__device__ __nv_bfloat16 g_B2h[9 * 32 * 64];
__device__ __nv_bfloat16 g_B2l[9 * 32 * 64];

// ============================ CSR build ====================================
__global__ void zero_cnt_k() {
    int i = blockIdx.x * blockDim.x + threadIdx.x;
    if (i < NSEG) g_cnt[i] = 0;
}

__global__ void count_k(const int* __restrict__ ei,
                        const int* __restrict__ et) {
    int e = blockIdx.x * blockDim.x + threadIdx.x;
    if (e < N_EDGES) {
        int dst = ei[N_EDGES + e];
        int r   = et[e];
        atomicAdd(&g_cnt[dst * N_RELS + r], 1);
    }
}

__global__ void scan1_k() {
    __shared__ int sh[256];
    int t = threadIdx.x;
    int base = blockIdx.x * SCAN_CHUNK + t * 8;
    int v[8]; int s = 0;
    #pragma unroll
    for (int i = 0; i < 8; i++) {
        int idx = base + i;
        v[i] = (idx < NSEG) ? g_cnt[idx] : 0;
        s += v[i];
    }
    sh[t] = s;
    __syncthreads();
    for (int off = 1; off < 256; off <<= 1) {
        int u = (t >= off) ? sh[t - off] : 0;
        __syncthreads();
        sh[t] += u;
        __syncthreads();
    }
    if (t == 255) g_bsum[blockIdx.x] = sh[255];
    int run = sh[t] - s;
    #pragma unroll
    for (int i = 0; i < 8; i++) {
        if (base + i < NSEG) g_off[base + i] = run;
        run += v[i];
    }
}

__global__ void scan2_k() {
    __shared__ int sh[256];
    int t = threadIdx.x;
    int s = (t < NCHUNK) ? g_bsum[t] : 0;
    sh[t] = s;
    __syncthreads();
    for (int off = 1; off < 256; off <<= 1) {
        int u = (t >= off) ? sh[t - off] : 0;
        __syncthreads();
        sh[t] += u;
        __syncthreads();
    }
    if (t < NCHUNK) g_bsum[t] = sh[t] - s;
}

__global__ void scan3_k() {   // finalize offsets + cursors + inv
    int i = blockIdx.x * blockDim.x + threadIdx.x;
    if (i < NSEG) {
        int o = g_off[i] + g_bsum[i >> 11];
        g_off[i] = o;
        g_cur[i] = o;
        int c = g_cnt[i];
        g_inv[i] = 1.0f / (float)(c > 1 ? c : 1);
    }
}

__global__ void fill_k(const int* __restrict__ ei,
                       const int* __restrict__ et) {
    int e = blockIdx.x * blockDim.x + threadIdx.x;
    if (e < N_EDGES) {
        int src = ei[e];
        int dst = ei[N_EDGES + e];
        int r   = et[e];
        int p = atomicAdd(&g_cur[dst * N_RELS + r], 1);
        g_srcs[p] = src;
    }
}

// ---- Weight transpose + bf16 split for BOTH layers in one launch ----------
// idx space: [0, 9*64*64) -> layer1, [9*64*64, +9*32*64) -> layer2
__global__ void wconv_k(const float* __restrict__ root1,
                        const float* __restrict__ W1,
                        const float* __restrict__ root2,
                        const float* __restrict__ W2,
                        __nv_bfloat16* __restrict__ b1h,
                        __nv_bfloat16* __restrict__ b1l,
                        __nv_bfloat16* __restrict__ b2h,
                        __nv_bfloat16* __restrict__ b2l) {
    int i = blockIdx.x * blockDim.x + threadIdx.x;
    constexpr int T1 = 9 * 64 * 64;
    constexpr int T2 = 9 * 32 * 64;
    if (i >= T1 + T2) return;
    float w;
    __nv_bfloat16* bh;
    __nv_bfloat16* bl;
    int o;
    if (i < T1) {
        int k = i & 63;
        int n = (i >> 6) & 63;
        int s = i / (64 * 64);
        w = (s == 0) ? root1[k * 64 + n] : W1[((size_t)(s - 1) * 64 + k) * 64 + n];
        bh = b1h; bl = b1l; o = i;
    } else {
        int j = i - T1;
        int k = j & 63;
        int n = (j >> 6) & 31;
        int s = j / (64 * 32);
        w = (s == 0) ? root2[k * 32 + n] : W2[((size_t)(s - 1) * 64 + k) * 32 + n];
        bh = b2h; bl = b2l; o = j;
    }
    __nv_bfloat16 h = __float2bfloat16(w);
    bh[o] = h;
    bl[o] = __float2bfloat16(w - __bfloat162float(h));
}

// ============================ mma helpers ==================================
__device__ __forceinline__ unsigned smem_u32(const void* p) {
    unsigned a;
    asm("{ .reg .u64 t; cvta.to.shared.u64 t, %1; cvt.u32.u64 %0, t; }"
        : "=r"(a) : "l"(p));
    return a;
}

__device__ __forceinline__ void ldsm4(unsigned& r0, unsigned& r1,
                                      unsigned& r2, unsigned& r3, unsigned a) {
    asm volatile("ldmatrix.sync.aligned.m8n8.x4.shared.b16 {%0,%1,%2,%3}, [%4];"
                 : "=r"(r0), "=r"(r1), "=r"(r2), "=r"(r3) : "r"(a));
}

__device__ __forceinline__ void mma_bf16(float* c, const unsigned* a,
                                         unsigned b0, unsigned b1) {
    asm volatile(
        "mma.sync.aligned.m16n8k16.row.col.f32.bf16.bf16.f32 "
        "{%0,%1,%2,%3}, {%4,%5,%6,%7}, {%8,%9}, {%0,%1,%2,%3};"
        : "+f"(c[0]), "+f"(c[1]), "+f"(c[2]), "+f"(c[3])
        : "r"(a[0]), "r"(a[1]), "r"(a[2]), "r"(a[3]), "r"(b0), "r"(b1));
}

__device__ __forceinline__ void cp_async16(unsigned dst, const void* src) {
    asm volatile("cp.async.cg.shared.global [%0], [%1], 16;"
                 :: "r"(dst), "l"(src) : "memory");
}
__device__ __forceinline__ void cp_commit() {
    asm volatile("cp.async.commit_group;" ::: "memory");
}
__device__ __forceinline__ void cp_wait0() {
    asm volatile("cp.async.wait_group 0;" ::: "memory");
}

// split 16 fp32 -> bf16 hi/lo (two uint4 each)
__device__ __forceinline__ void split16(const float* v, uint4* hp, uint4* lp) {
    unsigned h[8], l[8];
    #pragma unroll
    for (int j = 0; j < 8; j++) {
        float a = v[2 * j], b = v[2 * j + 1];
        __nv_bfloat16 ha = __float2bfloat16(a);
        __nv_bfloat16 hb = __float2bfloat16(b);
        __nv_bfloat162 hh; hh.x = ha; hh.y = hb;
        __nv_bfloat162 ll;
        ll.x = __float2bfloat16(a - __bfloat162float(ha));
        ll.y = __float2bfloat16(b - __bfloat162float(hb));
        h[j] = *reinterpret_cast<unsigned*>(&hh);
        l[j] = *reinterpret_cast<unsigned*>(&ll);
    }
    hp[0] = make_uint4(h[0], h[1], h[2], h[3]);
    hp[1] = make_uint4(h[4], h[5], h[6], h[7]);
    lp[0] = make_uint4(l[0], l[1], l[2], l[3]);
    lp[1] = make_uint4(l[4], l[5], l[6], l[7]);
}

// ============================ fused gather + mma GEMM ======================
// Tile: 64 rows x FOUT cols, 256 threads (8 warps as 4x2), occupancy 3.
// 9 segments of K=64; A built by CSR gather (split bf16), B via cp.async from
// preconverted globals. Double buffered, one barrier per segment.
#define ASTRB 144
template<int FOUT, bool RELU>
__global__ __launch_bounds__(256, 3)
void rgcn_mma_k(const float* __restrict__ X,
                const __nv_bfloat16* __restrict__ Bh,   // [9][FOUT][64]
                const __nv_bfloat16* __restrict__ Bl,
                const float* __restrict__ bias,
                float* __restrict__ out) {
    extern __shared__ char smem[];
    constexpr int APART = 64 * ASTRB;          // 9216 B
    constexpr int BPART = FOUT * ASTRB;
    constexpr int OFF_B = 4 * APART;

    const int tid = threadIdx.x;
    const int wid = tid >> 5;
    const int lane = tid & 31;
    const int row0 = blockIdx.x * 64;
    const unsigned sb = smem_u32(smem);

    // gather role: 4 threads per row, 16 floats each
    const int rrow = tid >> 2;
    const int q = tid & 3;
    const int grow = row0 + rrow;

    int off8[8], cnt8[8];
    float inv8[8];
    if (grow < N_NODES) {
        const int4* op = (const int4*)(g_off + grow * N_RELS);
        const int4* cp = (const int4*)(g_cnt + grow * N_RELS);
        const float4* ip = (const float4*)(g_inv + grow * N_RELS);
        int4 o0 = op[0], o1 = op[1];
        int4 c0 = cp[0], c1 = cp[1];
        float4 i0 = ip[0], i1 = ip[1];
        off8[0]=o0.x; off8[1]=o0.y; off8[2]=o0.z; off8[3]=o0.w;
        off8[4]=o1.x; off8[5]=o1.y; off8[6]=o1.z; off8[7]=o1.w;
        cnt8[0]=c0.x; cnt8[1]=c0.y; cnt8[2]=c0.z; cnt8[3]=c0.w;
        cnt8[4]=c1.x; cnt8[5]=c1.y; cnt8[6]=c1.z; cnt8[7]=c1.w;
        inv8[0]=i0.x; inv8[1]=i0.y; inv8[2]=i0.z; inv8[3]=i0.w;
        inv8[4]=i1.x; inv8[5]=i1.y; inv8[6]=i1.z; inv8[7]=i1.w;
    } else {
        #pragma unroll
        for (int r = 0; r < 8; r++) { off8[r] = 0; cnt8[r] = 0; inv8[r] = 0.f; }
    }

    auto produce = [&](int s, int buf) {
        // ---- B: cp.async preconverted [FOUT][64] bf16 rows ----
        {
            unsigned Bhs = sb + OFF_B + (2 * buf + 0) * BPART;
            unsigned Bls = sb + OFF_B + (2 * buf + 1) * BPART;
            const uint4* sh = (const uint4*)(Bh + (size_t)s * FOUT * 64);
            const uint4* sl = (const uint4*)(Bl + (size_t)s * FOUT * 64);
            #pragma unroll
            for (int i = 0; i < FOUT / 32; i++) {
                int lin = tid + i * 256;
                int n = lin >> 3, c = lin & 7;
                unsigned d = n * ASTRB + c * 16;
                cp_async16(Bhs + d, sh + lin);
                cp_async16(Bls + d, sl + lin);
            }
            cp_commit();
        }

        // ---- A: gather (seg 0 = identity), split, store ----
        float v[16];
        if (s == 0) {
            if (grow < N_NODES) {
                const float4* xp = (const float4*)(X + (size_t)grow * 64) + q * 4;
                #pragma unroll
                for (int i = 0; i < 4; i++) {
                    float4 t = xp[i];
                    v[4*i] = t.x; v[4*i+1] = t.y; v[4*i+2] = t.z; v[4*i+3] = t.w;
                }
            } else {
                #pragma unroll
                for (int i = 0; i < 16; i++) v[i] = 0.f;
            }
        } else {
            #pragma unroll
            for (int i = 0; i < 16; i++) v[i] = 0.f;
            int rel = s - 1;
            int start = off8[rel], cnt = cnt8[rel];
            float w = inv8[rel];
            int src_next = (cnt > 0) ? g_srcs[start] : 0;   // prefetch head
            for (int i = 0; i < cnt; i++) {
                int src = src_next;
                if (i + 1 < cnt) src_next = g_srcs[start + i + 1];  // overlap
                const float4* xp = (const float4*)(X + (size_t)src * 64) + q * 4;
                #pragma unroll
                for (int j = 0; j < 4; j++) {
                    float4 t = xp[j];
                    v[4*j] += t.x; v[4*j+1] += t.y; v[4*j+2] += t.z; v[4*j+3] += t.w;
                }
            }
            #pragma unroll
            for (int i = 0; i < 16; i++) v[i] *= w;
        }
        uint4 hp[2], lp[2];
        split16(v, hp, lp);
        char* Ahi = smem + (2 * buf + 0) * APART;
        char* Alo = smem + (2 * buf + 1) * APART;
        unsigned o = rrow * ASTRB + q * 32;
        *(uint4*)(Ahi + o) = hp[0];
        *(uint4*)(Ahi + o + 16) = hp[1];
        *(uint4*)(Alo + o) = lp[0];
        *(uint4*)(Alo + o + 16) = lp[1];
    };

    // warp tile: 16 rows x (FOUT/2) cols
    const int warpRow = wid & 3;
    const int warpCol = wid >> 2;
    constexpr int NT = FOUT / 16;        // n-tiles (8 cols each): 4 or 2
    float c[NT][4];
    #pragma unroll
    for (int t = 0; t < NT; t++)
        #pragma unroll
        for (int j = 0; j < 4; j++) c[t][j] = 0.f;

    const int lrow = (lane & 7) + ((lane >> 3) & 1) * 8;
    const unsigned lkoff = (lane >> 4) * 16;

    produce(0, 0);
    cp_wait0();
    __syncthreads();

    for (int seg = 0; seg < 9; seg++) {
        const int b = seg & 1;
        if (seg < 8) produce(seg + 1, b ^ 1);

        const unsigned Ahi = sb + (2 * b + 0) * APART;
        const unsigned Alo = sb + (2 * b + 1) * APART;
        const unsigned Bhi = sb + OFF_B + (2 * b + 0) * BPART;
        const unsigned Blo = sb + OFF_B + (2 * b + 1) * BPART;
        const unsigned aoff = (warpRow * 16 + lrow) * ASTRB + lkoff;

        #pragma unroll
        for (int kc = 0; kc < 4; kc++) {
            unsigned ah[4], al[4];
            ldsm4(ah[0], ah[1], ah[2], ah[3], Ahi + aoff + kc * 32);
            ldsm4(al[0], al[1], al[2], al[3], Alo + aoff + kc * 32);
            #pragma unroll
            for (int p = 0; p < NT / 2; p++) {
                unsigned boff = (warpCol * (FOUT / 2) + p * 16 + lrow) * ASTRB
                              + lkoff + kc * 32;
                unsigned bh0, bh1, bh2, bh3, bl0, bl1, bl2, bl3;
                ldsm4(bh0, bh1, bh2, bh3, Bhi + boff);
                ldsm4(bl0, bl1, bl2, bl3, Blo + boff);
                mma_bf16(c[2*p],     ah, bh0, bh2);
                mma_bf16(c[2*p],     ah, bl0, bl2);
                mma_bf16(c[2*p],     al, bh0, bh2);
                mma_bf16(c[2*p + 1], ah, bh1, bh3);
                mma_bf16(c[2*p + 1], ah, bl1, bl3);
                mma_bf16(c[2*p + 1], al, bh1, bh3);
            }
        }
        if (seg < 8) cp_wait0();
        __syncthreads();
    }

    // epilogue
    const int er = row0 + warpRow * 16 + (lane >> 2);
    #pragma unroll
    for (int t = 0; t < NT; t++) {
        int cc = warpCol * (FOUT / 2) + t * 8 + (lane & 3) * 2;
        float2 bv = *(const float2*)&bias[cc];
        if (er < N_NODES) {
            float2 o = make_float2(c[t][0] + bv.x, c[t][1] + bv.y);
            if (RELU) { o.x = fmaxf(o.x, 0.f); o.y = fmaxf(o.y, 0.f); }
            *(float2*)&out[(size_t)er * FOUT + cc] = o;
        }
        if (er + 8 < N_NODES) {
            float2 o = make_float2(c[t][2] + bv.x, c[t][3] + bv.y);
            if (RELU) { o.x = fmaxf(o.x, 0.f); o.y = fmaxf(o.y, 0.f); }
            *(float2*)&out[(size_t)(er + 8) * FOUT + cc] = o;
        }
    }
}

// ---------------------------------------------------------------------------
extern "C" void kernel_launch(void* const* d_in, const int* in_sizes, int n_in,
                              void* d_out, int out_size) {
    const float* x     = (const float*)d_in[0];
    const int*   ei    = (const int*)d_in[1];   // int32 on device (JAX x64 off)
    const int*   et    = (const int*)d_in[2];
    const float* W1    = (const float*)d_in[3];
    const float* root1 = (const float*)d_in[4];
    const float* b1    = (const float*)d_in[5];
    const float* W2    = (const float*)d_in[6];
    const float* root2 = (const float*)d_in[7];
    const float* b2    = (const float*)d_in[8];
    float* out = (float*)d_out;

    float* h_ptr = nullptr;
    cudaGetSymbolAddress((void**)&h_ptr, g_h);
    __nv_bfloat16 *b1h, *b1l, *b2h, *b2l;
    cudaGetSymbolAddress((void**)&b1h, g_B1h);
    cudaGetSymbolAddress((void**)&b1l, g_B1l);
    cudaGetSymbolAddress((void**)&b2h, g_B2h);
    cudaGetSymbolAddress((void**)&b2l, g_B2l);

    constexpr int SMEM1 = 4 * 64 * ASTRB + 4 * 64 * ASTRB;  // 73728
    constexpr int SMEM2 = 4 * 64 * ASTRB + 4 * 32 * ASTRB;  // 55296
    cudaFuncSetAttribute(rgcn_mma_k<64, true>,
                         cudaFuncAttributeMaxDynamicSharedMemorySize, SMEM1);
    cudaFuncSetAttribute(rgcn_mma_k<32, false>,
                         cudaFuncAttributeMaxDynamicSharedMemorySize, SMEM2);

    const int segBlocks  = (NSEG + 255) / 256;
    const int edgeBlocks = (N_EDGES + 255) / 256;
    const int mmaBlocks  = (N_NODES + 63) / 64;
    constexpr int WTOT = 9 * 64 * 64 + 9 * 32 * 64;

    // CSR build (shared by both layers) + weight preconversion
    zero_cnt_k<<<segBlocks, 256>>>();
    count_k<<<edgeBlocks, 256>>>(ei, et);
    scan1_k<<<NCHUNK, 256>>>();
    scan2_k<<<1, 256>>>();
    scan3_k<<<segBlocks, 256>>>();
    fill_k<<<edgeBlocks, 256>>>(ei, et);
    wconv_k<<<(WTOT + 255) / 256, 256>>>(root1, W1, root2, W2, b1h, b1l, b2h, b2l);

    // Layer 1 (fused gather + split-bf16 mma.sync GEMM)
    rgcn_mma_k<64, true><<<mmaBlocks, 256, SMEM1>>>(x, b1h, b1l, b1, h_ptr);

    // Layer 2
    rgcn_mma_k<32, false><<<mmaBlocks, 256, SMEM2>>>(h_ptr, b2h, b2l, b2, out);
}

// round 12
// speedup vs baseline: 4.1746x; 1.0017x over previous
#include <cuda_runtime.h>
#include <cuda_bf16.h>

#define N_NODES 50000
#define N_EDGES 800000
#define N_RELS  8
#define NSEG    (N_NODES * N_RELS)
#define SCAN_CHUNK 2048
#define NCHUNK  ((NSEG + SCAN_CHUNK - 1) / SCAN_CHUNK)   // 196

// Scratch (device globals; no allocation allowed anywhere)
__device__ float g_h[(size_t)N_NODES * 64];
__device__ int   g_cnt[NSEG];
__device__ float g_inv[NSEG];
__device__ int   g_off[NSEG];
__device__ int   g_cur[NSEG];
__device__ int   g_bsum[NCHUNK];
__device__ int   g_srcs[N_EDGES];
// Pre-split weights, layout [seg][n][k] (n-major, k contiguous), bf16
__device__ __nv_bfloat16 g_B1h[9 * 64 * 64];
__device__ __nv_bfloat16 g_B1l[9 * 64 * 64];
__device__ __nv_bfloat16 g_B2h[9 * 32 * 64];
__device__ __nv_bfloat16 g_B2l[9 * 32 * 64];

// ===== merged: zero g_cnt + weight transpose/split (index-partitioned) =====
__global__ void zw_k(const float* __restrict__ root1,
                     const float* __restrict__ W1,
                     const float* __restrict__ root2,
                     const float* __restrict__ W2,
                     __nv_bfloat16* __restrict__ b1h,
                     __nv_bfloat16* __restrict__ b1l,
                     __nv_bfloat16* __restrict__ b2h,
                     __nv_bfloat16* __restrict__ b2l) {
    int i = blockIdx.x * blockDim.x + threadIdx.x;
    constexpr int T1 = 9 * 64 * 64;
    constexpr int T2 = 9 * 32 * 64;
    if (i < NSEG) {
        g_cnt[i] = 0;
        return;
    }
    int j = i - NSEG;
    if (j >= T1 + T2) return;
    float w;
    __nv_bfloat16* bh;
    __nv_bfloat16* bl;
    int o;
    if (j < T1) {
        int k = j & 63;
        int n = (j >> 6) & 63;
        int s = j / (64 * 64);
        w = (s == 0) ? root1[k * 64 + n] : W1[((size_t)(s - 1) * 64 + k) * 64 + n];
        bh = b1h; bl = b1l; o = j;
    } else {
        int m = j - T1;
        int k = m & 63;
        int n = (m >> 6) & 31;
        int s = m / (64 * 32);
        w = (s == 0) ? root2[k * 32 + n] : W2[((size_t)(s - 1) * 64 + k) * 32 + n];
        bh = b2h; bl = b2l; o = m;
    }
    __nv_bfloat16 h = __float2bfloat16(w);
    bh[o] = h;
    bl[o] = __float2bfloat16(w - __bfloat162float(h));
}

__global__ void count_k(const int* __restrict__ ei,
                        const int* __restrict__ et) {
    int e = blockIdx.x * blockDim.x + threadIdx.x;
    if (e < N_EDGES) {
        int dst = ei[N_EDGES + e];
        int r   = et[e];
        atomicAdd(&g_cnt[dst * N_RELS + r], 1);
    }
}

__global__ void scan1_k() {
    __shared__ int sh[256];
    int t = threadIdx.x;
    int base = blockIdx.x * SCAN_CHUNK + t * 8;
    int v[8]; int s = 0;
    #pragma unroll
    for (int i = 0; i < 8; i++) {
        int idx = base + i;
        v[i] = (idx < NSEG) ? g_cnt[idx] : 0;
        s += v[i];
    }
    sh[t] = s;
    __syncthreads();
    for (int off = 1; off < 256; off <<= 1) {
        int u = (t >= off) ? sh[t - off] : 0;
        __syncthreads();
        sh[t] += u;
        __syncthreads();
    }
    if (t == 255) g_bsum[blockIdx.x] = sh[255];
    int run = sh[t] - s;
    #pragma unroll
    for (int i = 0; i < 8; i++) {
        if (base + i < NSEG) g_off[base + i] = run;
        run += v[i];
    }
}

// merged scan2+scan3: every block redundantly scans the 196 chunk sums in
// smem, then finalizes its 256 segment entries (off/cur/inv).
__global__ void scan23_k() {
    __shared__ int sh[256];
    int t = threadIdx.x;
    int s = (t < NCHUNK) ? g_bsum[t] : 0;
    sh[t] = s;
    __syncthreads();
    for (int off = 1; off < 256; off <<= 1) {
        int u = (t >= off) ? sh[t - off] : 0;
        __syncthreads();
        sh[t] += u;
        __syncthreads();
    }
    int excl = sh[t] - s;
    __syncthreads();
    sh[t] = excl;        // exclusive prefix of chunk totals
    __syncthreads();
    int i = blockIdx.x * blockDim.x + t;
    if (i < NSEG) {
        int o = g_off[i] + sh[i >> 11];   // SCAN_CHUNK = 2048 = 1<<11
        g_off[i] = o;
        g_cur[i] = o;
        int c = g_cnt[i];
        g_inv[i] = 1.0f / (float)(c > 1 ? c : 1);
    }
}

__global__ void fill_k(const int* __restrict__ ei,
                       const int* __restrict__ et) {
    int e = blockIdx.x * blockDim.x + threadIdx.x;
    if (e < N_EDGES) {
        int src = ei[e];
        int dst = ei[N_EDGES + e];
        int r   = et[e];
        int p = atomicAdd(&g_cur[dst * N_RELS + r], 1);
        g_srcs[p] = src;
    }
}

// ============================ mma helpers ==================================
__device__ __forceinline__ unsigned smem_u32(const void* p) {
    unsigned a;
    asm("{ .reg .u64 t; cvta.to.shared.u64 t, %1; cvt.u32.u64 %0, t; }"
        : "=r"(a) : "l"(p));
    return a;
}

__device__ __forceinline__ void ldsm4(unsigned& r0, unsigned& r1,
                                      unsigned& r2, unsigned& r3, unsigned a) {
    asm volatile("ldmatrix.sync.aligned.m8n8.x4.shared.b16 {%0,%1,%2,%3}, [%4];"
                 : "=r"(r0), "=r"(r1), "=r"(r2), "=r"(r3) : "r"(a));
}

__device__ __forceinline__ void mma_bf16(float* c, const unsigned* a,
                                         unsigned b0, unsigned b1) {
    asm volatile(
        "mma.sync.aligned.m16n8k16.row.col.f32.bf16.bf16.f32 "
        "{%0,%1,%2,%3}, {%4,%5,%6,%7}, {%8,%9}, {%0,%1,%2,%3};"
        : "+f"(c[0]), "+f"(c[1]), "+f"(c[2]), "+f"(c[3])
        : "r"(a[0]), "r"(a[1]), "r"(a[2]), "r"(a[3]), "r"(b0), "r"(b1));
}

__device__ __forceinline__ void cp_async16(unsigned dst, const void* src) {
    asm volatile("cp.async.cg.shared.global [%0], [%1], 16;"
                 :: "r"(dst), "l"(src) : "memory");
}
__device__ __forceinline__ void cp_commit() {
    asm volatile("cp.async.commit_group;" ::: "memory");
}
__device__ __forceinline__ void cp_wait0() {
    asm volatile("cp.async.wait_group 0;" ::: "memory");
}

// split 16 fp32 -> bf16 hi/lo (two uint4 each)
__device__ __forceinline__ void split16(const float* v, uint4* hp, uint4* lp) {
    unsigned h[8], l[8];
    #pragma unroll
    for (int j = 0; j < 8; j++) {
        float a = v[2 * j], b = v[2 * j + 1];
        __nv_bfloat16 ha = __float2bfloat16(a);
        __nv_bfloat16 hb = __float2bfloat16(b);
        __nv_bfloat162 hh; hh.x = ha; hh.y = hb;
        __nv_bfloat162 ll;
        ll.x = __float2bfloat16(a - __bfloat162float(ha));
        ll.y = __float2bfloat16(b - __bfloat162float(hb));
        h[j] = *reinterpret_cast<unsigned*>(&hh);
        l[j] = *reinterpret_cast<unsigned*>(&ll);
    }
    hp[0] = make_uint4(h[0], h[1], h[2], h[3]);
    hp[1] = make_uint4(h[4], h[5], h[6], h[7]);
    lp[0] = make_uint4(l[0], l[1], l[2], l[3]);
    lp[1] = make_uint4(l[4], l[5], l[6], l[7]);
}

// ============================ fused gather + mma GEMM ======================
// Tile: 64 rows x FOUT cols, 256 threads (8 warps as 4x2), occupancy 3.
// 9 segments of K=64; A built by CSR gather (split bf16), B via cp.async from
// preconverted globals. Double buffered, one barrier per segment.
#define ASTRB 144
template<int FOUT, bool RELU>
__global__ __launch_bounds__(256, 3)
void rgcn_mma_k(const float* __restrict__ X,
                const __nv_bfloat16* __restrict__ Bh,   // [9][FOUT][64]
                const __nv_bfloat16* __restrict__ Bl,
                const float* __restrict__ bias,
                float* __restrict__ out) {
    extern __shared__ char smem[];
    constexpr int APART = 64 * ASTRB;          // 9216 B
    constexpr int BPART = FOUT * ASTRB;
    constexpr int OFF_B = 4 * APART;

    const int tid = threadIdx.x;
    const int wid = tid >> 5;
    const int lane = tid & 31;
    const int row0 = blockIdx.x * 64;
    const unsigned sb = smem_u32(smem);

    // gather role: 4 threads per row, 16 floats each
    const int rrow = tid >> 2;
    const int q = tid & 3;
    const int grow = row0 + rrow;

    int off8[8], cnt8[8];
    float inv8[8];
    if (grow < N_NODES) {
        const int4* op = (const int4*)(g_off + grow * N_RELS);
        const int4* cp = (const int4*)(g_cnt + grow * N_RELS);
        const float4* ip = (const float4*)(g_inv + grow * N_RELS);
        int4 o0 = op[0], o1 = op[1];
        int4 c0 = cp[0], c1 = cp[1];
        float4 i0 = ip[0], i1 = ip[1];
        off8[0]=o0.x; off8[1]=o0.y; off8[2]=o0.z; off8[3]=o0.w;
        off8[4]=o1.x; off8[5]=o1.y; off8[6]=o1.z; off8[7]=o1.w;
        cnt8[0]=c0.x; cnt8[1]=c0.y; cnt8[2]=c0.z; cnt8[3]=c0.w;
        cnt8[4]=c1.x; cnt8[5]=c1.y; cnt8[6]=c1.z; cnt8[7]=c1.w;
        inv8[0]=i0.x; inv8[1]=i0.y; inv8[2]=i0.z; inv8[3]=i0.w;
        inv8[4]=i1.x; inv8[5]=i1.y; inv8[6]=i1.z; inv8[7]=i1.w;
    } else {
        #pragma unroll
        for (int r = 0; r < 8; r++) { off8[r] = 0; cnt8[r] = 0; inv8[r] = 0.f; }
    }

    auto produce = [&](int s, int buf) {
        // ---- B: cp.async preconverted [FOUT][64] bf16 rows ----
        {
            unsigned Bhs = sb + OFF_B + (2 * buf + 0) * BPART;
            unsigned Bls = sb + OFF_B + (2 * buf + 1) * BPART;
            const uint4* sh = (const uint4*)(Bh + (size_t)s * FOUT * 64);
            const uint4* sl = (const uint4*)(Bl + (size_t)s * FOUT * 64);
            #pragma unroll
            for (int i = 0; i < FOUT / 32; i++) {
                int lin = tid + i * 256;
                int n = lin >> 3, c = lin & 7;
                unsigned d = n * ASTRB + c * 16;
                cp_async16(Bhs + d, sh + lin);
                cp_async16(Bls + d, sl + lin);
            }
            cp_commit();
        }

        // ---- A: gather (seg 0 = identity), split, store ----
        float v[16];
        if (s == 0) {
            if (grow < N_NODES) {
                const float4* xp = (const float4*)(X + (size_t)grow * 64) + q * 4;
                #pragma unroll
                for (int i = 0; i < 4; i++) {
                    float4 t = xp[i];
                    v[4*i] = t.x; v[4*i+1] = t.y; v[4*i+2] = t.z; v[4*i+3] = t.w;
                }
            } else {
                #pragma unroll
                for (int i = 0; i < 16; i++) v[i] = 0.f;
            }
        } else {
            #pragma unroll
            for (int i = 0; i < 16; i++) v[i] = 0.f;
            int rel = s - 1;
            int start = off8[rel], cnt = cnt8[rel];
            float w = inv8[rel];
            int src_next = (cnt > 0) ? g_srcs[start] : 0;   // prefetch head
            for (int i = 0; i < cnt; i++) {
                int src = src_next;
                if (i + 1 < cnt) src_next = g_srcs[start + i + 1];  // overlap
                const float4* xp = (const float4*)(X + (size_t)src * 64) + q * 4;
                #pragma unroll
                for (int j = 0; j < 4; j++) {
                    float4 t = xp[j];
                    v[4*j] += t.x; v[4*j+1] += t.y; v[4*j+2] += t.z; v[4*j+3] += t.w;
                }
            }
            #pragma unroll
            for (int i = 0; i < 16; i++) v[i] *= w;
        }
        uint4 hp[2], lp[2];
        split16(v, hp, lp);
        char* Ahi = smem + (2 * buf + 0) * APART;
        char* Alo = smem + (2 * buf + 1) * APART;
        unsigned o = rrow * ASTRB + q * 32;
        *(uint4*)(Ahi + o) = hp[0];
        *(uint4*)(Ahi + o + 16) = hp[1];
        *(uint4*)(Alo + o) = lp[0];
        *(uint4*)(Alo + o + 16) = lp[1];
    };

    // warp tile: 16 rows x (FOUT/2) cols
    const int warpRow = wid & 3;
    const int warpCol = wid >> 2;
    constexpr int NT = FOUT / 16;        // n-tiles (8 cols each): 4 or 2
    float c[NT][4];
    #pragma unroll
    for (int t = 0; t < NT; t++)
        #pragma unroll
        for (int j = 0; j < 4; j++) c[t][j] = 0.f;

    const int lrow = (lane & 7) + ((lane >> 3) & 1) * 8;
    const unsigned lkoff = (lane >> 4) * 16;

    produce(0, 0);
    cp_wait0();
    __syncthreads();

    for (int seg = 0; seg < 9; seg++) {
        const int b = seg & 1;
        if (seg < 8) produce(seg + 1, b ^ 1);

        const unsigned Ahi = sb + (2 * b + 0) * APART;
        const unsigned Alo = sb + (2 * b + 1) * APART;
        const unsigned Bhi = sb + OFF_B + (2 * b + 0) * BPART;
        const unsigned Blo = sb + OFF_B + (2 * b + 1) * BPART;
        const unsigned aoff = (warpRow * 16 + lrow) * ASTRB + lkoff;

        #pragma unroll
        for (int kc = 0; kc < 4; kc++) {
            unsigned ah[4], al[4];
            ldsm4(ah[0], ah[1], ah[2], ah[3], Ahi + aoff + kc * 32);
            ldsm4(al[0], al[1], al[2], al[3], Alo + aoff + kc * 32);
            #pragma unroll
            for (int p = 0; p < NT / 2; p++) {
                unsigned boff = (warpCol * (FOUT / 2) + p * 16 + lrow) * ASTRB
                              + lkoff + kc * 32;
                unsigned bh0, bh1, bh2, bh3, bl0, bl1, bl2, bl3;
                ldsm4(bh0, bh1, bh2, bh3, Bhi + boff);
                ldsm4(bl0, bl1, bl2, bl3, Blo + boff);
                mma_bf16(c[2*p],     ah, bh0, bh2);
                mma_bf16(c[2*p],     ah, bl0, bl2);
                mma_bf16(c[2*p],     al, bh0, bh2);
                mma_bf16(c[2*p + 1], ah, bh1, bh3);
                mma_bf16(c[2*p + 1], ah, bl1, bl3);
                mma_bf16(c[2*p + 1], al, bh1, bh3);
            }
        }
        if (seg < 8) cp_wait0();
        __syncthreads();
    }

    // epilogue
    const int er = row0 + warpRow * 16 + (lane >> 2);
    #pragma unroll
    for (int t = 0; t < NT; t++) {
        int cc = warpCol * (FOUT / 2) + t * 8 + (lane & 3) * 2;
        float2 bv = *(const float2*)&bias[cc];
        if (er < N_NODES) {
            float2 o = make_float2(c[t][0] + bv.x, c[t][1] + bv.y);
            if (RELU) { o.x = fmaxf(o.x, 0.f); o.y = fmaxf(o.y, 0.f); }
            *(float2*)&out[(size_t)er * FOUT + cc] = o;
        }
        if (er + 8 < N_NODES) {
            float2 o = make_float2(c[t][2] + bv.x, c[t][3] + bv.y);
            if (RELU) { o.x = fmaxf(o.x, 0.f); o.y = fmaxf(o.y, 0.f); }
            *(float2*)&out[(size_t)(er + 8) * FOUT + cc] = o;
        }
    }
}

// ---------------------------------------------------------------------------
extern "C" void kernel_launch(void* const* d_in, const int* in_sizes, int n_in,
                              void* d_out, int out_size) {
    const float* x     = (const float*)d_in[0];
    const int*   ei    = (const int*)d_in[1];   // int32 on device (JAX x64 off)
    const int*   et    = (const int*)d_in[2];
    const float* W1    = (const float*)d_in[3];
    const float* root1 = (const float*)d_in[4];
    const float* b1    = (const float*)d_in[5];
    const float* W2    = (const float*)d_in[6];
    const float* root2 = (const float*)d_in[7];
    const float* b2    = (const float*)d_in[8];
    float* out = (float*)d_out;

    float* h_ptr = nullptr;
    cudaGetSymbolAddress((void**)&h_ptr, g_h);
    __nv_bfloat16 *b1h, *b1l, *b2h, *b2l;
    cudaGetSymbolAddress((void**)&b1h, g_B1h);
    cudaGetSymbolAddress((void**)&b1l, g_B1l);
    cudaGetSymbolAddress((void**)&b2h, g_B2h);
    cudaGetSymbolAddress((void**)&b2l, g_B2l);

    constexpr int SMEM1 = 4 * 64 * ASTRB + 4 * 64 * ASTRB;  // 73728
    constexpr int SMEM2 = 4 * 64 * ASTRB + 4 * 32 * ASTRB;  // 55296
    cudaFuncSetAttribute(rgcn_mma_k<64, true>,
                         cudaFuncAttributeMaxDynamicSharedMemorySize, SMEM1);
    cudaFuncSetAttribute(rgcn_mma_k<32, false>,
                         cudaFuncAttributeMaxDynamicSharedMemorySize, SMEM2);

    const int segBlocks  = (NSEG + 255) / 256;
    const int edgeBlocks = (N_EDGES + 255) / 256;
    const int mmaBlocks  = (N_NODES + 63) / 64;
    constexpr int WTOT = 9 * 64 * 64 + 9 * 32 * 64;
    const int zwBlocks   = (NSEG + WTOT + 255) / 256;

    // CSR build + weight preconversion (5 launches; mma1 lands at index 5
    // so ncu -s 5 -c 1 captures it)
    zw_k<<<zwBlocks, 256>>>(root1, W1, root2, W2, b1h, b1l, b2h, b2l);
    count_k<<<edgeBlocks, 256>>>(ei, et);
    scan1_k<<<NCHUNK, 256>>>();
    scan23_k<<<segBlocks, 256>>>();
    fill_k<<<edgeBlocks, 256>>>(ei, et);

    // Layer 1 (fused gather + split-bf16 mma.sync GEMM)
    rgcn_mma_k<64, true><<<mmaBlocks, 256, SMEM1>>>(x, b1h, b1l, b1, h_ptr);

    // Layer 2
    rgcn_mma_k<32, false><<<mmaBlocks, 256, SMEM2>>>(h_ptr, b2h, b2l, b2, out);
}